// round 3
// baseline (speedup 1.0000x reference)
#include <cuda_runtime.h>
#include <math.h>

#define BATCH  256
#define PRIOR  60
#define FRAMES 240
#define POSE   768
#define CHUNK  10
#define PRED   180
#define EPS    1e-5f

// ---------------- scratch (static device globals; no allocation) ----------------
__device__ float g_p1[BATCH * PRED * POSE];    // conv1 output
__device__ float g_p2[BATCH * PRED * POSE];    // conv2 output / updated p
__device__ float g_h1[BATCH * FRAMES * POSE];  // post-header intermediate
__device__ float g_tmp[BATCH * POSE];
__device__ float g_mem[BATCH * POSE];
__device__ float g_mem2[BATCH * POSE];
__device__ float g_s1[BATCH * CHUNK];
__device__ float g_penc[BATCH * CHUNK];
__device__ float g_t[POSE * CHUNK];

// ---------------- generic NT GEMM: C[M,N] = A[M,K] @ W[N,K]^T + bias[N] ----------------
// AMODE 0: A row m at A + m*lda
// AMODE 1: concat rows: m -> (b=m/FRAMES, f=m%FRAMES); f<PRIOR ? x-row : p-row
template <int BM, int BN, int BK, int TM, int TN, int AMODE>
__global__ __launch_bounds__((BM / TM) * (BN / TN))
void sgemm_nt(const float* __restrict__ A, long lda,
              const float* __restrict__ A2,
              const float* __restrict__ W,
              const float* __restrict__ bias,
              float* __restrict__ C, int ldc,
              int M, int N, int K)
{
    constexpr int THREADS = (BM / TM) * (BN / TN);
    constexpr int ASLOTS = BM * BK / THREADS;
    constexpr int BSLOTS = BN * BK / THREADS;

    __shared__ float As[BK][BM + 4];
    __shared__ float Bs[BK][BN + 4];

    const int tid = threadIdx.x;
    const int bm = blockIdx.y * BM;
    const int bn = blockIdx.x * BN;
    const int tx = tid % (BN / TN);
    const int ty = tid / (BN / TN);

    // Precompute per-slot row pointers (fixed across the K loop)
    const float* arow[ASLOTS];
    int akl[ASLOTS], aml[ASLOTS];
#pragma unroll
    for (int j = 0; j < ASLOTS; ++j) {
        int s = tid + j * THREADS;
        akl[j] = s % BK;
        aml[j] = s / BK;
        int m = bm + aml[j];
        const float* rp;
        if (AMODE == 1) {
            int bb = m / FRAMES, f = m % FRAMES;
            rp = (f < PRIOR) ? (A2 + ((long)bb * PRIOR + f) * POSE)
                             : (A  + ((long)bb * PRED  + (f - PRIOR)) * POSE);
        } else {
            rp = A + (long)m * lda;
        }
        arow[j] = rp;
    }
    const float* brow[BSLOTS];
    int bkl[BSLOTS], bnl[BSLOTS];
#pragma unroll
    for (int j = 0; j < BSLOTS; ++j) {
        int s = tid + j * THREADS;
        bkl[j] = s % BK;
        bnl[j] = s / BK;
        brow[j] = W + (long)(bn + bnl[j]) * K;
    }

    float acc[TM][TN];
#pragma unroll
    for (int i = 0; i < TM; ++i)
#pragma unroll
        for (int j = 0; j < TN; ++j) acc[i][j] = 0.f;

    for (int k0 = 0; k0 < K; k0 += BK) {
#pragma unroll
        for (int j = 0; j < ASLOTS; ++j) {
            int k = k0 + akl[j];
            int m = bm + aml[j];
            float v = (k < K && m < M) ? arow[j][k] : 0.f;
            As[akl[j]][aml[j]] = v;
        }
#pragma unroll
        for (int j = 0; j < BSLOTS; ++j) {
            int k = k0 + bkl[j];
            float v = (k < K && (bn + bnl[j]) < N) ? brow[j][k] : 0.f;
            Bs[bkl[j]][bnl[j]] = v;
        }
        __syncthreads();
#pragma unroll
        for (int kk = 0; kk < BK; ++kk) {
            float a[TM], b[TN];
#pragma unroll
            for (int i = 0; i < TM; ++i) a[i] = As[kk][ty * TM + i];
#pragma unroll
            for (int j = 0; j < TN; ++j) b[j] = Bs[kk][tx * TN + j];
#pragma unroll
            for (int i = 0; i < TM; ++i)
#pragma unroll
                for (int j = 0; j < TN; ++j) acc[i][j] += a[i] * b[j];
        }
        __syncthreads();
    }

#pragma unroll
    for (int i = 0; i < TM; ++i) {
        int m = bm + ty * TM + i;
        if (m >= M) continue;
#pragma unroll
        for (int j = 0; j < TN; ++j) {
            int n = bn + tx * TN + j;
            if (n < N) C[(long)m * ldc + n] = acc[i][j] + bias[n];
        }
    }
}

// ---------------- conv1d(k=3,p=1) over pose axis + ReLU + BN (eval) ----------------
// Per batch b: P[b][o][h] = bn(relu( sum_{i,kk} W[o, i*3+kk] * X[b, i, h+kk-1] + cb[o] ))
template <int BM, int BN, int BK, int TM, int TN>
__global__ __launch_bounds__((BM / TM) * (BN / TN))
void conv_bn_kernel(const float* __restrict__ Wt, int CIN,
                    const float* __restrict__ X,
                    const float* __restrict__ cb,
                    const float* __restrict__ gg, const float* __restrict__ bb,
                    const float* __restrict__ mm, const float* __restrict__ vv,
                    float* __restrict__ P)
{
    constexpr int THREADS = (BM / TM) * (BN / TN);
    static_assert(THREADS == BN, "B-tile loader assumes THREADS == BN");
    constexpr int ASLOTS = BM * BK / THREADS;

    const int K = CIN * 3;
    __shared__ float As[BK][BM + 4];
    __shared__ float Bs[BK][BN + 4];

    const int tid = threadIdx.x;
    const int bm = blockIdx.y * BM;
    const int bn = blockIdx.x * BN;
    const int bz = blockIdx.z;
    const float* Xb = X + (long)bz * CIN * POSE;
    const int tx = tid % (BN / TN);
    const int ty = tid / (BN / TN);

    float acc[TM][TN];
#pragma unroll
    for (int i = 0; i < TM; ++i)
#pragma unroll
        for (int j = 0; j < TN; ++j) acc[i][j] = 0.f;

    for (int k0 = 0; k0 < K; k0 += BK) {
#pragma unroll
        for (int j = 0; j < ASLOTS; ++j) {
            int s = tid + j * THREADS;
            int kl = s % BK, ml = s / BK;
            int k = k0 + kl, o = bm + ml;
            float v = (k < K && o < PRED) ? Wt[(long)o * K + k] : 0.f;
            As[kl][ml] = v;
        }
#pragma unroll
        for (int j = 0; j < BK; ++j) {
            int kk = k0 + j;
            float v = 0.f;
            if (kk < K) {
                int i = kk / 3;
                int dlt = kk - 3 * i - 1;
                int h = bn + tid + dlt;
                if (h >= 0 && h < POSE) v = Xb[(long)i * POSE + h];
            }
            Bs[j][tid] = v;
        }
        __syncthreads();
#pragma unroll
        for (int kk = 0; kk < BK; ++kk) {
            float a[TM], b[TN];
#pragma unroll
            for (int i = 0; i < TM; ++i) a[i] = As[kk][ty * TM + i];
#pragma unroll
            for (int j = 0; j < TN; ++j) b[j] = Bs[kk][tx * TN + j];
#pragma unroll
            for (int i = 0; i < TM; ++i)
#pragma unroll
                for (int j = 0; j < TN; ++j) acc[i][j] += a[i] * b[j];
        }
        __syncthreads();
    }

#pragma unroll
    for (int i = 0; i < TM; ++i) {
        int o = bm + ty * TM + i;
        if (o >= PRED) continue;
        float sc = gg[o] * rsqrtf(vv[o] + EPS);
        float mo = mm[o], bo = bb[o], co = cb[o];
        float* Pr = P + (long)bz * PRED * POSE + (long)o * POSE;
#pragma unroll
        for (int j = 0; j < TN; ++j) {
            int h = bn + tx * TN + j;
            float y = acc[i][j] + co;
            y = fmaxf(y, 0.f);
            Pr[h] = (y - mo) * sc + bo;
        }
    }
}

// ---------------- SP memory gate ----------------
// score[b,c] = <mem[b,:], p[b,c,:]>; sig = sigmoid(score);
// p[b,c,:] = sig*p + (1-sig)*mem   for c < CHUNK
__global__ void sp_gate_kernel(const float* __restrict__ mem, float* __restrict__ p)
{
    int b = blockIdx.x;
    int tid = threadIdx.x;          // 320 threads = 10 warps
    int w = tid >> 5, lane = tid & 31;
    __shared__ float sig_s[CHUNK];

    const float* pm = mem + (long)b * POSE;
    const float* pc = p + (long)b * PRED * POSE + (long)w * POSE;
    float s = 0.f;
    for (int d = lane; d < POSE; d += 32) s += pm[d] * pc[d];
#pragma unroll
    for (int o = 16; o; o >>= 1) s += __shfl_xor_sync(0xffffffffu, s, o);
    if (lane == 0) sig_s[w] = 1.f / (1.f + expf(-s));
    __syncthreads();

    float* pb = p + (long)b * PRED * POSE;
    for (int idx = tid; idx < CHUNK * POSE; idx += 320) {
        int c = idx / POSE, d = idx - c * POSE;
        float g = sig_s[c];
        pb[idx] = g * pb[idx] + (1.f - g) * pm[d];
    }
}

// ---------------- TM: t[d,c] = sum_b mem2[b,d] * penc[b,c] ----------------
__global__ void tm_t_kernel(const float* __restrict__ mem2,
                            const float* __restrict__ penc,
                            float* __restrict__ t)
{
    int d = blockIdx.x;             // POSE blocks, 64 threads
    int tid = threadIdx.x;
    float acc[CHUNK];
#pragma unroll
    for (int c = 0; c < CHUNK; ++c) acc[c] = 0.f;
    for (int b = tid; b < BATCH; b += 64) {
        float m = mem2[(long)b * POSE + d];
        const float* pr = penc + (long)b * CHUNK;
#pragma unroll
        for (int c = 0; c < CHUNK; ++c) acc[c] += m * pr[c];
    }
    __shared__ float red[64][CHUNK];
#pragma unroll
    for (int c = 0; c < CHUNK; ++c) red[tid][c] = acc[c];
    __syncthreads();
    for (int off = 32; off >= 1; off >>= 1) {
        if (tid < off)
#pragma unroll
            for (int c = 0; c < CHUNK; ++c) red[tid][c] += red[tid + off][c];
        __syncthreads();
    }
    if (tid == 0)
#pragma unroll
        for (int c = 0; c < CHUNK; ++c) t[(long)d * CHUNK + c] = red[0][c];
}

// ---------------- TM apply: score2 = mem2 @ t; softmax over c; p[:, :CHUNK] *= (1+soft) ----
__global__ void tm_apply_kernel(const float* __restrict__ mem2,
                                const float* __restrict__ t,
                                float* __restrict__ p)
{
    int b = blockIdx.x;
    int tid = threadIdx.x;          // 256 threads
    float acc[CHUNK];
#pragma unroll
    for (int c = 0; c < CHUNK; ++c) acc[c] = 0.f;
    const float* mb = mem2 + (long)b * POSE;
    for (int d = tid; d < POSE; d += 256) {
        float m = mb[d];
        const float* tr = t + (long)d * CHUNK;
#pragma unroll
        for (int c = 0; c < CHUNK; ++c) acc[c] += m * tr[c];
    }
    __shared__ float red[256][CHUNK];
    __shared__ float soft[CHUNK];
#pragma unroll
    for (int c = 0; c < CHUNK; ++c) red[tid][c] = acc[c];
    __syncthreads();
    for (int off = 128; off >= 1; off >>= 1) {
        if (tid < off)
#pragma unroll
            for (int c = 0; c < CHUNK; ++c) red[tid][c] += red[tid + off][c];
        __syncthreads();
    }
    if (tid == 0) {
        float mx = red[0][0];
#pragma unroll
        for (int c = 1; c < CHUNK; ++c) mx = fmaxf(mx, red[0][c]);
        float sum = 0.f;
        float e[CHUNK];
#pragma unroll
        for (int c = 0; c < CHUNK; ++c) { e[c] = expf(red[0][c] - mx); sum += e[c]; }
        float inv = 1.f / sum;
#pragma unroll
        for (int c = 0; c < CHUNK; ++c) soft[c] = e[c] * inv;
    }
    __syncthreads();
    float* pb = p + (long)b * PRED * POSE;
    for (int idx = tid; idx < CHUNK * POSE; idx += 256) {
        int c = idx / POSE;
        pb[idx] *= (1.f + soft[c]);
    }
}

// ---------------- host launcher ----------------
extern "C" void kernel_launch(void* const* d_in, const int* in_sizes, int n_in,
                              void* d_out, int out_size)
{
    (void)in_sizes; (void)n_in; (void)out_size;

    const float* x       = (const float*)d_in[0];
    const float* conv1_w = (const float*)d_in[1];
    const float* conv1_b = (const float*)d_in[2];
    const float* bn1_g   = (const float*)d_in[3];
    const float* bn1_b   = (const float*)d_in[4];
    const float* bn1_m   = (const float*)d_in[5];
    const float* bn1_v   = (const float*)d_in[6];
    const float* conv2_w = (const float*)d_in[7];
    const float* conv2_b = (const float*)d_in[8];
    const float* bn2_g   = (const float*)d_in[9];
    const float* bn2_b   = (const float*)d_in[10];
    const float* bn2_m   = (const float*)d_in[11];
    const float* bn2_v   = (const float*)d_in[12];
    const float* sp_w1   = (const float*)d_in[13];
    const float* sp_b1   = (const float*)d_in[14];
    const float* sp_w2   = (const float*)d_in[15];
    const float* sp_b2   = (const float*)d_in[16];
    const float* tmc_w1  = (const float*)d_in[17];
    const float* tmc_b1  = (const float*)d_in[18];
    const float* tmc_w2  = (const float*)d_in[19];
    const float* tmc_b2  = (const float*)d_in[20];
    const float* tmm_w1  = (const float*)d_in[21];
    const float* tmm_b1  = (const float*)d_in[22];
    const float* tmm_w2  = (const float*)d_in[23];
    const float* tmm_b2  = (const float*)d_in[24];
    const float* post_w1 = (const float*)d_in[25];
    const float* post_b1 = (const float*)d_in[26];
    const float* post_w2 = (const float*)d_in[27];
    const float* post_b2 = (const float*)d_in[28];

    float *p1, *p2, *h1, *tmp, *mem, *mem2, *s1, *penc, *t;
    cudaGetSymbolAddress((void**)&p1,   g_p1);
    cudaGetSymbolAddress((void**)&p2,   g_p2);
    cudaGetSymbolAddress((void**)&h1,   g_h1);
    cudaGetSymbolAddress((void**)&tmp,  g_tmp);
    cudaGetSymbolAddress((void**)&mem,  g_mem);
    cudaGetSymbolAddress((void**)&mem2, g_mem2);
    cudaGetSymbolAddress((void**)&s1,   g_s1);
    cudaGetSymbolAddress((void**)&penc, g_penc);
    cudaGetSymbolAddress((void**)&t,    g_t);

    // 1) conv1 + relu + bn1 : x[B,60,768] -> p1[B,180,768]
    {
        dim3 grid(POSE / 128, (PRED + 63) / 64, BATCH);
        conv_bn_kernel<64, 128, 16, 8, 8><<<grid, 128>>>(
            conv1_w, PRIOR, x, conv1_b, bn1_g, bn1_b, bn1_m, bn1_v, p1);
    }
    // 2) conv2 + relu + bn2 : p1 -> p2
    {
        dim3 grid(POSE / 128, (PRED + 63) / 64, BATCH);
        conv_bn_kernel<64, 128, 16, 8, 8><<<grid, 128>>>(
            conv2_w, PRED, p1, conv2_b, bn2_g, bn2_b, bn2_m, bn2_v, p2);
    }
    // 3) sp encoder: tail -> tmp -> mem
    sgemm_nt<32, 128, 16, 4, 8, 0><<<dim3(POSE / 128, BATCH / 32), 128>>>(
        x + (PRIOR - CHUNK) * POSE, (long)PRIOR * POSE, nullptr,
        sp_w1, sp_b1, tmp, POSE, BATCH, POSE, CHUNK * POSE);
    sgemm_nt<32, 128, 16, 4, 8, 0><<<dim3(POSE / 128, BATCH / 32), 128>>>(
        tmp, POSE, nullptr, sp_w2, sp_b2, mem, POSE, BATCH, POSE, POSE);
    // 4) sigmoid gate on p2[:, :CHUNK]
    sp_gate_kernel<<<BATCH, CHUNK * 32>>>(mem, p2);
    // 5) tmc encoder: tail -> tmp -> mem2
    sgemm_nt<32, 128, 16, 4, 8, 0><<<dim3(POSE / 128, BATCH / 32), 128>>>(
        x + (PRIOR - CHUNK) * POSE, (long)PRIOR * POSE, nullptr,
        tmc_w1, tmc_b1, tmp, POSE, BATCH, POSE, CHUNK * POSE);
    sgemm_nt<32, 128, 16, 4, 8, 0><<<dim3(POSE / 128, BATCH / 32), 128>>>(
        tmp, POSE, nullptr, tmc_w2, tmc_b2, mem2, POSE, BATCH, POSE, POSE);
    // 6) tmm encoder on updated p2[:, :CHUNK] -> s1 -> penc
    sgemm_nt<32, 128, 16, 4, 8, 0><<<dim3(1, BATCH / 32), 128>>>(
        p2, (long)PRED * POSE, nullptr,
        tmm_w1, tmm_b1, s1, CHUNK, BATCH, CHUNK, CHUNK * POSE);
    sgemm_nt<32, 128, 16, 4, 8, 0><<<dim3(1, BATCH / 32), 128>>>(
        s1, CHUNK, nullptr, tmm_w2, tmm_b2, penc, CHUNK, BATCH, CHUNK, CHUNK);
    // 7) t = mem2^T @ penc ; score2 = mem2 @ t ; softmax ; scale p2[:, :CHUNK]
    tm_t_kernel<<<POSE, 64>>>(mem2, penc, t);
    tm_apply_kernel<<<BATCH, 256>>>(mem2, t, p2);
    // 8) post header: concat(x, p2) @ W1^T + b1 -> h1 ; h1 @ W2^T + b2 -> out
    sgemm_nt<128, 128, 16, 8, 8, 1><<<dim3(POSE / 128, BATCH * FRAMES / 128), 256>>>(
        p2, 0, x, post_w1, post_b1, h1, POSE, BATCH * FRAMES, POSE, POSE);
    sgemm_nt<128, 128, 16, 8, 8, 0><<<dim3(POSE / 128, BATCH * FRAMES / 128), 256>>>(
        h1, POSE, nullptr, post_w2, post_b2, (float*)d_out, POSE, BATCH * FRAMES, POSE, POSE);
}

// round 7
// speedup vs baseline: 1.8051x; 1.8051x over previous
#include <cuda_runtime.h>
#include <cuda_bf16.h>
#include <math.h>
#include <stdint.h>

#define BATCH  256
#define PRIOR  60
#define FRAMES 240
#define POSE   768
#define CHUNK  10
#define PRED   180
#define EPS    1e-5f
#define MROWS  (BATCH * FRAMES)
#define CIN1P  64
#define CIN2P  192
#define KC1    (3 * CIN1P)
#define KC2    (3 * CIN2P)
#define XTR    770

// ---------------- scratch (zero-initialized device globals; padding rows/channels are
// never written by any kernel, so they stay zero forever -> deterministic) -------------
__device__ unsigned short g_Ahi[MROWS * POSE], g_Alo[MROWS * POSE];
__device__ unsigned short g_Hhi[MROWS * POSE], g_Hlo[MROWS * POSE];
__device__ unsigned short g_W1hi[POSE * POSE], g_W1lo[POSE * POSE];
__device__ unsigned short g_W2hi[POSE * POSE], g_W2lo[POSE * POSE];
__device__ unsigned short g_Xthi[BATCH * XTR * CIN1P], g_Xtlo[BATCH * XTR * CIN1P];
__device__ unsigned short g_P1hi[BATCH * XTR * CIN2P], g_P1lo[BATCH * XTR * CIN2P];
__device__ unsigned short g_Wc1hi[256 * KC1], g_Wc1lo[256 * KC1];
__device__ unsigned short g_Wc2hi[256 * KC2], g_Wc2lo[256 * KC2];
__device__ float g_p2[BATCH * PRED * POSE];
__device__ float g_tmp[BATCH * POSE];
__device__ float g_mem[BATCH * POSE];
__device__ float g_mem2[BATCH * POSE];
__device__ float g_s1[BATCH * CHUNK];
__device__ float g_penc[BATCH * CHUNK];
__device__ float g_t[POSE * CHUNK];

// ---------------- helpers ----------------
__device__ __forceinline__ uint32_t smem_u32(const void* p) {
    uint32_t a;
    asm("{ .reg .u64 t; cvta.to.shared.u64 t, %1; cvt.u32.u64 %0, t; }" : "=r"(a) : "l"(p));
    return a;
}

#define LDSM_X4(r0, r1, r2, r3, addr) \
    asm volatile("ldmatrix.sync.aligned.m8n8.x4.shared.b16 {%0, %1, %2, %3}, [%4];" \
        : "=r"(r0), "=r"(r1), "=r"(r2), "=r"(r3) : "r"(addr))

__device__ __forceinline__ void mma16816(float c[4], uint32_t a0, uint32_t a1, uint32_t a2, uint32_t a3,
                                         uint32_t b0, uint32_t b1) {
    asm volatile("mma.sync.aligned.m16n8k16.row.col.f32.bf16.bf16.f32 "
                 "{%0, %1, %2, %3}, {%4, %5, %6, %7}, {%8, %9}, {%0, %1, %2, %3};"
                 : "+f"(c[0]), "+f"(c[1]), "+f"(c[2]), "+f"(c[3])
                 : "r"(a0), "r"(a1), "r"(a2), "r"(a3), "r"(b0), "r"(b1));
}

__device__ __forceinline__ void split_bf16(float v, unsigned short* hp, unsigned short* lp) {
    __nv_bfloat16 h = __float2bfloat16(v);
    __nv_bfloat16 l = __float2bfloat16(v - __bfloat162float(h));
    *hp = *(unsigned short*)&h;
    *lp = *(unsigned short*)&l;
}
__device__ __forceinline__ unsigned int split_pack(float v0, float v1, unsigned int* lo) {
    unsigned short h0, l0, h1, l1;
    split_bf16(v0, &h0, &l0);
    split_bf16(v1, &h1, &l1);
    *lo = (unsigned int)l0 | ((unsigned int)l1 << 16);
    return (unsigned int)h0 | ((unsigned int)h1 << 16);
}

// ---------------- HMMA hi/lo NT GEMM: C[128x128 tile] = A[128,K] @ B[128rows,K]^T ------
// EPI 0: +bias(n) -> fp32 outf (ld POSE)
// EPI 1: +bias(n) -> bf16 hi/lo outhi/outlo (ld POSE)
// EPI 2: +convbias(m), relu, BN(m) -> transposed bf16 hi/lo P1T[bz][h+1][och] (ld CIN2P)
// EPI 3: +convbias(m), relu, BN(m) -> fp32 channel-major p2[bz][och][h]
// CONVB: B row r, k -> act[(bz*XTR + n0 + r + dlt)*CINp + i], k = dlt*CINp + i
template <int EPI, bool CONVB>
__global__ __launch_bounds__(256)
void mma_gemm(const unsigned short* __restrict__ Ahi, const unsigned short* __restrict__ Alo,
              const unsigned short* __restrict__ Bhi, const unsigned short* __restrict__ Blo,
              int K, int CINp,
              const float* __restrict__ bias,
              const float* __restrict__ bng, const float* __restrict__ bnb,
              const float* __restrict__ bnm, const float* __restrict__ bnv,
              float* __restrict__ outf,
              unsigned short* __restrict__ outhi, unsigned short* __restrict__ outlo)
{
    constexpr int BM = 128, BN = 128, BK = 32, LDS = BK + 8;
    __shared__ unsigned short sAh[BM * LDS], sAl[BM * LDS];
    __shared__ unsigned short sBh[BN * LDS], sBl[BN * LDS];

    const int tid = threadIdx.x;
    const int lane = tid & 31;
    const int w = tid >> 5;
    const int wm = w >> 2;          // 0..1 -> 64 rows each
    const int wn = w & 3;           // 0..3 -> 32 cols each
    const int m0 = blockIdx.y * BM;
    const int n0 = blockIdx.x * BN;
    const int bz = blockIdx.z;

    const uint32_t uAh = smem_u32(sAh), uAl = smem_u32(sAl);
    const uint32_t uBh = smem_u32(sBh), uBl = smem_u32(sBl);

    // per-lane ldmatrix row/col offsets
    const int aRow = wm * 64 + (lane & 7) + ((lane >> 3) & 1) * 8;  // + mi*16
    const int aCol = ((lane >> 4) & 1) * 8;                         // + kk
    const int bRow = wn * 32 + (lane & 7) + ((lane >> 4) & 1) * 8;  // + nio*16
    const int bCol = ((lane >> 3) & 1) * 8;                         // + kk

    float c[4][4][4];
#pragma unroll
    for (int i = 0; i < 4; ++i)
#pragma unroll
        for (int j = 0; j < 4; ++j)
#pragma unroll
            for (int q = 0; q < 4; ++q) c[i][j][q] = 0.f;

    const int ldr = tid >> 2;           // 0..63? no: 256 threads -> idx pattern below
    const int ldc = tid & 3;

    for (int k0 = 0; k0 < K; k0 += BK) {
        int dlt = 0, i0 = k0;
        if (CONVB) { dlt = k0 / CINp; i0 = k0 - dlt * CINp; }
        // load A/B tiles: 128 rows x 32 cols each, hi+lo. 512 segs of 8 bf16 per operand.
#pragma unroll
        for (int u = 0; u < 2; ++u) {
            int r = ldr + u * 64;
            size_t ga = (size_t)(m0 + r) * K + k0 + ldc * 8;
            *(uint4*)&sAh[r * LDS + ldc * 8] = *(const uint4*)(Ahi + ga);
            *(uint4*)&sAl[r * LDS + ldc * 8] = *(const uint4*)(Alo + ga);
            size_t gb;
            if (CONVB) gb = (size_t)((size_t)bz * XTR + n0 + r + dlt) * CINp + i0 + ldc * 8;
            else       gb = (size_t)(n0 + r) * K + k0 + ldc * 8;
            *(uint4*)&sBh[r * LDS + ldc * 8] = *(const uint4*)(Bhi + gb);
            *(uint4*)&sBl[r * LDS + ldc * 8] = *(const uint4*)(Blo + gb);
        }
        __syncthreads();

#pragma unroll
        for (int ks = 0; ks < 2; ++ks) {
            const int kk = ks * 16;
            uint32_t ah[4][4], al[4][4];
#pragma unroll
            for (int mi = 0; mi < 4; ++mi) {
                uint32_t off = (uint32_t)(((aRow + mi * 16) * LDS + kk + aCol) * 2);
                LDSM_X4(ah[mi][0], ah[mi][1], ah[mi][2], ah[mi][3], uAh + off);
                LDSM_X4(al[mi][0], al[mi][1], al[mi][2], al[mi][3], uAl + off);
            }
            uint32_t bh[4][2], bl[4][2];
#pragma unroll
            for (int nio = 0; nio < 2; ++nio) {
                uint32_t off = (uint32_t)(((bRow + nio * 16) * LDS + kk + bCol) * 2);
                uint32_t r0, r1, r2, r3;
                LDSM_X4(r0, r1, r2, r3, uBh + off);
                bh[nio * 2][0] = r0; bh[nio * 2][1] = r1;
                bh[nio * 2 + 1][0] = r2; bh[nio * 2 + 1][1] = r3;
                LDSM_X4(r0, r1, r2, r3, uBl + off);
                bl[nio * 2][0] = r0; bl[nio * 2][1] = r1;
                bl[nio * 2 + 1][0] = r2; bl[nio * 2 + 1][1] = r3;
            }
#pragma unroll
            for (int mi = 0; mi < 4; ++mi)
#pragma unroll
                for (int ni = 0; ni < 4; ++ni) {
                    mma16816(c[mi][ni], ah[mi][0], ah[mi][1], ah[mi][2], ah[mi][3],
                             bh[ni][0], bh[ni][1]);
                    mma16816(c[mi][ni], ah[mi][0], ah[mi][1], ah[mi][2], ah[mi][3],
                             bl[ni][0], bl[ni][1]);
                    mma16816(c[mi][ni], al[mi][0], al[mi][1], al[mi][2], al[mi][3],
                             bh[ni][0], bh[ni][1]);
                }
        }
        __syncthreads();
    }

    // ---------------- epilogue from fragments ----------------
    // frag (mi,ni): rows m0+wm*64+mi*16 + lane/4 (+8), cols n0+wn*32+ni*8 + (lane%4)*2 (+1)
#pragma unroll
    for (int mi = 0; mi < 4; ++mi) {
#pragma unroll
        for (int ni = 0; ni < 4; ++ni) {
            const int col = n0 + wn * 32 + ni * 8 + (lane & 3) * 2;
#pragma unroll
            for (int half = 0; half < 2; ++half) {
                const int row = m0 + wm * 64 + mi * 16 + (lane >> 2) + half * 8;
                const float v0r = c[mi][ni][half * 2];
                const float v1r = c[mi][ni][half * 2 + 1];
                if (EPI == 0) {
                    float2 v;
                    v.x = v0r + bias[col];
                    v.y = v1r + bias[col + 1];
                    *(float2*)(outf + (size_t)row * POSE + col) = v;
                } else if (EPI == 1) {
                    unsigned int lo;
                    unsigned int hi = split_pack(v0r + bias[col], v1r + bias[col + 1], &lo);
                    *(unsigned int*)(outhi + (size_t)row * POSE + col) = hi;
                    *(unsigned int*)(outlo + (size_t)row * POSE + col) = lo;
                } else {
                    const int och = row;
                    if (och < PRED) {
                        const float cb = bias[och];
                        const float sc = bng[och] * rsqrtf(bnv[och] + EPS);
                        const float mo = bnm[och], bo = bnb[och];
                        float v0 = (fmaxf(v0r + cb, 0.f) - mo) * sc + bo;
                        float v1 = (fmaxf(v1r + cb, 0.f) - mo) * sc + bo;
                        if (EPI == 3) {
                            float2 v; v.x = v0; v.y = v1;
                            *(float2*)(outf + (size_t)((size_t)bz * PRED + och) * POSE + col) = v;
                        } else {
                            size_t oi0 = (size_t)((size_t)bz * XTR + col + 1) * CIN2P + och;
                            size_t oi1 = (size_t)((size_t)bz * XTR + col + 2) * CIN2P + och;
                            split_bf16(v0, &outhi[oi0], &outlo[oi0]);
                            split_bf16(v1, &outhi[oi1], &outlo[oi1]);
                        }
                    }
                }
            }
        }
    }
}

// ---------------- conversion kernels ----------------
__global__ void cvt_flat(const float* __restrict__ s, unsigned short* __restrict__ hi,
                         unsigned short* __restrict__ lo, int n)
{
    for (int i = blockIdx.x * blockDim.x + threadIdx.x; i < n; i += gridDim.x * blockDim.x)
        split_bf16(s[i], &hi[i], &lo[i]);
}

__global__ void cvt_concat(const float* __restrict__ x, const float* __restrict__ p2,
                           unsigned short* __restrict__ hi, unsigned short* __restrict__ lo)
{
    int m = blockIdx.x;
    int b = m / FRAMES, f = m - b * FRAMES;
    const float* src = (f < PRIOR) ? x + ((size_t)b * PRIOR + f) * POSE
                                   : p2 + ((size_t)b * PRED + (f - PRIOR)) * POSE;
    size_t dst = (size_t)m * POSE;
    for (int ci = threadIdx.x; ci < POSE; ci += 256)
        split_bf16(src[ci], &hi[dst + ci], &lo[dst + ci]);
}

__global__ void cvt_convw(const float* __restrict__ wsrc, unsigned short* __restrict__ hi,
                          unsigned short* __restrict__ lo, int CIN, int CINp)
{
    int total = PRED * CIN * 3;
    int KC = 3 * CINp;
    for (int idx = blockIdx.x * blockDim.x + threadIdx.x; idx < total; idx += gridDim.x * blockDim.x) {
        int o = idx / (CIN * 3);
        int rem = idx - o * (CIN * 3);
        int i = rem / 3, d = rem - i * 3;
        size_t dst = (size_t)o * KC + (size_t)d * CINp + i;
        split_bf16(wsrc[idx], &hi[dst], &lo[dst]);
    }
}

__global__ void cvt_xT(const float* __restrict__ x, unsigned short* __restrict__ hi,
                       unsigned short* __restrict__ lo)
{
    __shared__ float t[64][65];
    int b = blockIdx.y, h0 = blockIdx.x * 64;
    for (int idx = threadIdx.x; idx < PRIOR * 64; idx += 256) {
        int i = idx >> 6, h = idx & 63;
        t[h][i] = x[((size_t)b * PRIOR + i) * POSE + h0 + h];
    }
    __syncthreads();
    for (int idx = threadIdx.x; idx < 64 * PRIOR; idx += 256) {
        int h = idx / PRIOR, i = idx - h * PRIOR;
        size_t dst = ((size_t)b * XTR + h0 + h + 1) * CIN1P + i;
        split_bf16(t[h][i], &hi[dst], &lo[dst]);
    }
}

// ---------------- FFMA NT GEMM (encoders) ----------------
template <int BM, int BN, int BK, int TM, int TN>
__global__ __launch_bounds__((BM / TM) * (BN / TN))
void sgemm_nt(const float* __restrict__ A, long lda,
              const float* __restrict__ W,
              const float* __restrict__ bias,
              float* __restrict__ C, int ldc,
              int M, int N, int K)
{
    constexpr int THREADS = (BM / TM) * (BN / TN);
    constexpr int ASLOTS = BM * BK / THREADS;
    constexpr int BSLOTS = BN * BK / THREADS;
    __shared__ float As[BK][BM + 4];
    __shared__ float Bs[BK][BN + 4];
    const int tid = threadIdx.x;
    const int bm = blockIdx.y * BM;
    const int bn = blockIdx.x * BN;
    const int tx = tid % (BN / TN);
    const int ty = tid / (BN / TN);

    float acc[TM][TN];
#pragma unroll
    for (int i = 0; i < TM; ++i)
#pragma unroll
        for (int j = 0; j < TN; ++j) acc[i][j] = 0.f;

    for (int k0 = 0; k0 < K; k0 += BK) {
#pragma unroll
        for (int j = 0; j < ASLOTS; ++j) {
            int s = tid + j * THREADS;
            int kl = s % BK, ml = s / BK;
            int k = k0 + kl, m = bm + ml;
            As[kl][ml] = (k < K && m < M) ? A[(long)m * lda + k] : 0.f;
        }
#pragma unroll
        for (int j = 0; j < BSLOTS; ++j) {
            int s = tid + j * THREADS;
            int kl = s % BK, nl = s / BK;
            int k = k0 + kl, n = bn + nl;
            Bs[kl][nl] = (k < K && n < N) ? W[(long)n * K + k] : 0.f;
        }
        __syncthreads();
#pragma unroll
        for (int kk = 0; kk < BK; ++kk) {
            float a[TM], b[TN];
#pragma unroll
            for (int i = 0; i < TM; ++i) a[i] = As[kk][ty * TM + i];
#pragma unroll
            for (int j = 0; j < TN; ++j) b[j] = Bs[kk][tx * TN + j];
#pragma unroll
            for (int i = 0; i < TM; ++i)
#pragma unroll
                for (int j = 0; j < TN; ++j) acc[i][j] += a[i] * b[j];
        }
        __syncthreads();
    }
#pragma unroll
    for (int i = 0; i < TM; ++i) {
        int m = bm + ty * TM + i;
        if (m >= M) continue;
#pragma unroll
        for (int j = 0; j < TN; ++j) {
            int n = bn + tx * TN + j;
            if (n < N) C[(long)m * ldc + n] = acc[i][j] + bias[n];
        }
    }
}

// ---------------- gate kernels ----------------
__global__ void sp_gate_kernel(const float* __restrict__ mem, float* __restrict__ p)
{
    int b = blockIdx.x;
    int tid = threadIdx.x;
    int w = tid >> 5, lane = tid & 31;
    __shared__ float sig_s[CHUNK];
    const float* pm = mem + (long)b * POSE;
    const float* pc = p + (long)b * PRED * POSE + (long)w * POSE;
    float s = 0.f;
    for (int d = lane; d < POSE; d += 32) s += pm[d] * pc[d];
#pragma unroll
    for (int o = 16; o; o >>= 1) s += __shfl_xor_sync(0xffffffffu, s, o);
    if (lane == 0) sig_s[w] = 1.f / (1.f + expf(-s));
    __syncthreads();
    float* pb = p + (long)b * PRED * POSE;
    for (int idx = tid; idx < CHUNK * POSE; idx += 320) {
        int cc = idx / POSE, d = idx - cc * POSE;
        float g = sig_s[cc];
        pb[idx] = g * pb[idx] + (1.f - g) * pm[d];
    }
}

__global__ void tm_t_kernel(const float* __restrict__ mem2, const float* __restrict__ penc,
                            float* __restrict__ t)
{
    int d = blockIdx.x;
    int tid = threadIdx.x;
    float acc[CHUNK];
#pragma unroll
    for (int cc = 0; cc < CHUNK; ++cc) acc[cc] = 0.f;
    for (int b = tid; b < BATCH; b += 64) {
        float m = mem2[(long)b * POSE + d];
        const float* pr = penc + (long)b * CHUNK;
#pragma unroll
        for (int cc = 0; cc < CHUNK; ++cc) acc[cc] += m * pr[cc];
    }
    __shared__ float red[64][CHUNK];
#pragma unroll
    for (int cc = 0; cc < CHUNK; ++cc) red[tid][cc] = acc[cc];
    __syncthreads();
    for (int off = 32; off >= 1; off >>= 1) {
        if (tid < off)
#pragma unroll
            for (int cc = 0; cc < CHUNK; ++cc) red[tid][cc] += red[tid + off][cc];
        __syncthreads();
    }
    if (tid == 0)
#pragma unroll
        for (int cc = 0; cc < CHUNK; ++cc) t[(long)d * CHUNK + cc] = red[0][cc];
}

__global__ void tm_apply_kernel(const float* __restrict__ mem2, const float* __restrict__ t,
                                float* __restrict__ p)
{
    int b = blockIdx.x;
    int tid = threadIdx.x;
    float acc[CHUNK];
#pragma unroll
    for (int cc = 0; cc < CHUNK; ++cc) acc[cc] = 0.f;
    const float* mb = mem2 + (long)b * POSE;
    for (int d = tid; d < POSE; d += 256) {
        float m = mb[d];
        const float* tr = t + (long)d * CHUNK;
#pragma unroll
        for (int cc = 0; cc < CHUNK; ++cc) acc[cc] += m * tr[cc];
    }
    __shared__ float red[256][CHUNK];
    __shared__ float soft[CHUNK];
#pragma unroll
    for (int cc = 0; cc < CHUNK; ++cc) red[tid][cc] = acc[cc];
    __syncthreads();
    for (int off = 128; off >= 1; off >>= 1) {
        if (tid < off)
#pragma unroll
            for (int cc = 0; cc < CHUNK; ++cc) red[tid][cc] += red[tid + off][cc];
        __syncthreads();
    }
    if (tid == 0) {
        float mx = red[0][0];
#pragma unroll
        for (int cc = 1; cc < CHUNK; ++cc) mx = fmaxf(mx, red[0][cc]);
        float sum = 0.f, e[CHUNK];
#pragma unroll
        for (int cc = 0; cc < CHUNK; ++cc) { e[cc] = expf(red[0][cc] - mx); sum += e[cc]; }
        float inv = 1.f / sum;
#pragma unroll
        for (int cc = 0; cc < CHUNK; ++cc) soft[cc] = e[cc] * inv;
    }
    __syncthreads();
    float* pb = p + (long)b * PRED * POSE;
    for (int idx = tid; idx < CHUNK * POSE; idx += 256) {
        int cc = idx / POSE;
        pb[idx] *= (1.f + soft[cc]);
    }
}

// ---------------- host launcher ----------------
extern "C" void kernel_launch(void* const* d_in, const int* in_sizes, int n_in,
                              void* d_out, int out_size)
{
    (void)in_sizes; (void)n_in; (void)out_size;
    const float* x       = (const float*)d_in[0];
    const float* conv1_w = (const float*)d_in[1];
    const float* conv1_b = (const float*)d_in[2];
    const float* bn1_g   = (const float*)d_in[3];
    const float* bn1_b   = (const float*)d_in[4];
    const float* bn1_m   = (const float*)d_in[5];
    const float* bn1_v   = (const float*)d_in[6];
    const float* conv2_w = (const float*)d_in[7];
    const float* conv2_b = (const float*)d_in[8];
    const float* bn2_g   = (const float*)d_in[9];
    const float* bn2_b   = (const float*)d_in[10];
    const float* bn2_m   = (const float*)d_in[11];
    const float* bn2_v   = (const float*)d_in[12];
    const float* sp_w1   = (const float*)d_in[13];
    const float* sp_b1   = (const float*)d_in[14];
    const float* sp_w2   = (const float*)d_in[15];
    const float* sp_b2   = (const float*)d_in[16];
    const float* tmc_w1  = (const float*)d_in[17];
    const float* tmc_b1  = (const float*)d_in[18];
    const float* tmc_w2  = (const float*)d_in[19];
    const float* tmc_b2  = (const float*)d_in[20];
    const float* tmm_w1  = (const float*)d_in[21];
    const float* tmm_b1  = (const float*)d_in[22];
    const float* tmm_w2  = (const float*)d_in[23];
    const float* tmm_b2  = (const float*)d_in[24];
    const float* post_w1 = (const float*)d_in[25];
    const float* post_b1 = (const float*)d_in[26];
    const float* post_w2 = (const float*)d_in[27];
    const float* post_b2 = (const float*)d_in[28];

    unsigned short *Ahi, *Alo, *Hhi, *Hlo, *W1hi, *W1lo, *W2hi, *W2lo;
    unsigned short *Xthi, *Xtlo, *P1hi, *P1lo, *Wc1hi, *Wc1lo, *Wc2hi, *Wc2lo;
    float *p2, *tmp, *mem, *mem2, *s1, *penc, *t;
    cudaGetSymbolAddress((void**)&Ahi, g_Ahi);   cudaGetSymbolAddress((void**)&Alo, g_Alo);
    cudaGetSymbolAddress((void**)&Hhi, g_Hhi);   cudaGetSymbolAddress((void**)&Hlo, g_Hlo);
    cudaGetSymbolAddress((void**)&W1hi, g_W1hi); cudaGetSymbolAddress((void**)&W1lo, g_W1lo);
    cudaGetSymbolAddress((void**)&W2hi, g_W2hi); cudaGetSymbolAddress((void**)&W2lo, g_W2lo);
    cudaGetSymbolAddress((void**)&Xthi, g_Xthi); cudaGetSymbolAddress((void**)&Xtlo, g_Xtlo);
    cudaGetSymbolAddress((void**)&P1hi, g_P1hi); cudaGetSymbolAddress((void**)&P1lo, g_P1lo);
    cudaGetSymbolAddress((void**)&Wc1hi, g_Wc1hi); cudaGetSymbolAddress((void**)&Wc1lo, g_Wc1lo);
    cudaGetSymbolAddress((void**)&Wc2hi, g_Wc2hi); cudaGetSymbolAddress((void**)&Wc2lo, g_Wc2lo);
    cudaGetSymbolAddress((void**)&p2, g_p2);
    cudaGetSymbolAddress((void**)&tmp, g_tmp);
    cudaGetSymbolAddress((void**)&mem, g_mem);
    cudaGetSymbolAddress((void**)&mem2, g_mem2);
    cudaGetSymbolAddress((void**)&s1, g_s1);
    cudaGetSymbolAddress((void**)&penc, g_penc);
    cudaGetSymbolAddress((void**)&t, g_t);

    // conversions
    cvt_flat<<<512, 256>>>(post_w1, W1hi, W1lo, POSE * POSE);
    cvt_flat<<<512, 256>>>(post_w2, W2hi, W2lo, POSE * POSE);
    cvt_convw<<<128, 256>>>(conv1_w, Wc1hi, Wc1lo, PRIOR, CIN1P);
    cvt_convw<<<256, 256>>>(conv2_w, Wc2hi, Wc2lo, PRED, CIN2P);
    cvt_xT<<<dim3(POSE / 64, BATCH), 256>>>(x, Xthi, Xtlo);

    // conv1: W[180(pad256),192] @ XT^T -> P1T bf16 hi/lo (relu+bn fused, transposed out)
    mma_gemm<2, true><<<dim3(POSE / 128, 2, BATCH), 256>>>(
        Wc1hi, Wc1lo, Xthi, Xtlo, KC1, CIN1P,
        conv1_b, bn1_g, bn1_b, bn1_m, bn1_v, nullptr, P1hi, P1lo);
    // conv2: W[180(pad256),576] @ P1T^T -> p2 fp32 (relu+bn fused)
    mma_gemm<3, true><<<dim3(POSE / 128, 2, BATCH), 256>>>(
        Wc2hi, Wc2lo, P1hi, P1lo, KC2, CIN2P,
        conv2_b, bn2_g, bn2_b, bn2_m, bn2_v, p2, nullptr, nullptr);

    // encoders (FFMA) + gates
    const float* tail = x + (PRIOR - CHUNK) * POSE;
    sgemm_nt<32, 128, 16, 4, 8><<<dim3(POSE / 128, BATCH / 32), 128>>>(
        tail, (long)PRIOR * POSE, sp_w1, sp_b1, tmp, POSE, BATCH, POSE, CHUNK * POSE);
    sgemm_nt<32, 128, 16, 4, 8><<<dim3(POSE / 128, BATCH / 32), 128>>>(
        tmp, POSE, sp_w2, sp_b2, mem, POSE, BATCH, POSE, POSE);
    sp_gate_kernel<<<BATCH, CHUNK * 32>>>(mem, p2);
    sgemm_nt<32, 128, 16, 4, 8><<<dim3(POSE / 128, BATCH / 32), 128>>>(
        tail, (long)PRIOR * POSE, tmc_w1, tmc_b1, tmp, POSE, BATCH, POSE, CHUNK * POSE);
    sgemm_nt<32, 128, 16, 4, 8><<<dim3(POSE / 128, BATCH / 32), 128>>>(
        tmp, POSE, tmc_w2, tmc_b2, mem2, POSE, BATCH, POSE, POSE);
    sgemm_nt<32, 128, 16, 4, 8><<<dim3(1, BATCH / 32), 128>>>(
        p2, (long)PRED * POSE, tmm_w1, tmm_b1, s1, CHUNK, BATCH, CHUNK, CHUNK * POSE);
    sgemm_nt<32, 128, 16, 4, 8><<<dim3(1, BATCH / 32), 128>>>(
        s1, CHUNK, tmm_w2, tmm_b2, penc, CHUNK, BATCH, CHUNK, CHUNK);
    tm_t_kernel<<<POSE, 64>>>(mem2, penc, t);
    tm_apply_kernel<<<BATCH, 256>>>(mem2, t, p2);

    // post header on HMMA tensor path
    cvt_concat<<<MROWS, 256>>>(x, p2, Ahi, Alo);
    mma_gemm<1, false><<<dim3(POSE / 128, MROWS / 128), 256>>>(
        Ahi, Alo, W1hi, W1lo, POSE, 0,
        post_b1, nullptr, nullptr, nullptr, nullptr, nullptr, Hhi, Hlo);
    mma_gemm<0, false><<<dim3(POSE / 128, MROWS / 128), 256>>>(
        Hhi, Hlo, W2hi, W2lo, POSE, 0,
        post_b2, nullptr, nullptr, nullptr, nullptr, (float*)d_out, nullptr, nullptr);
}

// round 8
// speedup vs baseline: 2.6662x; 1.4771x over previous
#include <cuda_runtime.h>
#include <cuda_bf16.h>
#include <math.h>
#include <stdint.h>

#define BATCH  256
#define PRIOR  60
#define FRAMES 240
#define POSE   768
#define CHUNK  10
#define PRED   180
#define EPS    1e-5f
#define MROWS  (BATCH * FRAMES)
#define CIN1P  64
#define CIN2P  192
#define KC1    (3 * CIN1P)
#define KC2    (3 * CIN2P)
#define XTR    770

// ---------------- scratch (zero-initialized device globals; padding rows/channels are
// never written by any kernel, so they stay zero forever -> deterministic) -------------
__device__ unsigned short g_Ahi[MROWS * POSE], g_Alo[MROWS * POSE];
__device__ unsigned short g_Hhi[MROWS * POSE], g_Hlo[MROWS * POSE];
__device__ unsigned short g_W1hi[POSE * POSE], g_W1lo[POSE * POSE];
__device__ unsigned short g_W2hi[POSE * POSE], g_W2lo[POSE * POSE];
__device__ unsigned short g_Xthi[BATCH * XTR * CIN1P], g_Xtlo[BATCH * XTR * CIN1P];
__device__ unsigned short g_P1hi[BATCH * XTR * CIN2P], g_P1lo[BATCH * XTR * CIN2P];
__device__ unsigned short g_Wc1hi[256 * KC1], g_Wc1lo[256 * KC1];
__device__ unsigned short g_Wc2hi[256 * KC2], g_Wc2lo[256 * KC2];
__device__ float g_p2[BATCH * PRED * POSE];
__device__ float g_tmp[BATCH * 2 * POSE];   // stacked sp|tmc layer-1 outputs, ld = 1536
__device__ float g_mem[BATCH * POSE];
__device__ float g_mem2[BATCH * POSE];
__device__ float g_s1[BATCH * CHUNK];
__device__ float g_penc[BATCH * CHUNK];
__device__ float g_t[POSE * CHUNK];

// ---------------- helpers ----------------
__device__ __forceinline__ uint32_t smem_u32(const void* p) {
    uint32_t a;
    asm("{ .reg .u64 t; cvta.to.shared.u64 t, %1; cvt.u32.u64 %0, t; }" : "=r"(a) : "l"(p));
    return a;
}
__device__ __forceinline__ void cp16(uint32_t dst, const void* src) {
    asm volatile("cp.async.cg.shared.global [%0], [%1], 16;" :: "r"(dst), "l"(src));
}

#define LDSM_X4(r0, r1, r2, r3, addr) \
    asm volatile("ldmatrix.sync.aligned.m8n8.x4.shared.b16 {%0, %1, %2, %3}, [%4];" \
        : "=r"(r0), "=r"(r1), "=r"(r2), "=r"(r3) : "r"(addr))

__device__ __forceinline__ void mma16816(float c[4], uint32_t a0, uint32_t a1, uint32_t a2, uint32_t a3,
                                         uint32_t b0, uint32_t b1) {
    asm volatile("mma.sync.aligned.m16n8k16.row.col.f32.bf16.bf16.f32 "
                 "{%0, %1, %2, %3}, {%4, %5, %6, %7}, {%8, %9}, {%0, %1, %2, %3};"
                 : "+f"(c[0]), "+f"(c[1]), "+f"(c[2]), "+f"(c[3])
                 : "r"(a0), "r"(a1), "r"(a2), "r"(a3), "r"(b0), "r"(b1));
}

__device__ __forceinline__ void split_bf16(float v, unsigned short* hp, unsigned short* lp) {
    __nv_bfloat16 h = __float2bfloat16(v);
    __nv_bfloat16 l = __float2bfloat16(v - __bfloat162float(h));
    *hp = *(unsigned short*)&h;
    *lp = *(unsigned short*)&l;
}
__device__ __forceinline__ unsigned int split_pack(float v0, float v1, unsigned int* lo) {
    unsigned short h0, l0, h1, l1;
    split_bf16(v0, &h0, &l0);
    split_bf16(v1, &h1, &l1);
    *lo = (unsigned int)l0 | ((unsigned int)l1 << 16);
    return (unsigned int)h0 | ((unsigned int)h1 << 16);
}

// ---------------- HMMA hi/lo NT GEMM (cp.async double-buffered) ------------------------
// C[128x128 tile] = A[128,K] @ B[128rows,K]^T   (3-pass: AhBh + AhBl + AlBh)
// EPI 0: +bias(n) -> fp32 outf (ld POSE)
// EPI 1: +bias(n) -> bf16 hi/lo outhi/outlo (ld POSE)
// EPI 2: +convbias(m), relu, BN(m) -> transposed bf16 hi/lo P1T[bz][h+1][och] (ld CIN2P)
// EPI 3: +convbias(m), relu, BN(m) -> fp32 channel-major p2[bz][och][h]
// CONVB: B row r, k -> act[(bz*XTR + n0 + r + dlt)*CINp + i], k = dlt*CINp + i
#define GBM 128
#define GBK 32
#define GLDS (GBK + 8)
#define GTILE (GBM * GLDS)                  // shorts per operand tile (5120)
#define GSTAGE_B (4 * GTILE * 2)            // bytes per stage (40960)
#define GSMEM_B (2 * GSTAGE_B)              // 81920

template <int EPI, bool CONVB>
__global__ __launch_bounds__(256)
void mma_gemm(const unsigned short* __restrict__ Ahi, const unsigned short* __restrict__ Alo,
              const unsigned short* __restrict__ Bhi, const unsigned short* __restrict__ Blo,
              int K, int CINp,
              const float* __restrict__ bias,
              const float* __restrict__ bng, const float* __restrict__ bnb,
              const float* __restrict__ bnm, const float* __restrict__ bnv,
              float* __restrict__ outf,
              unsigned short* __restrict__ outhi, unsigned short* __restrict__ outlo)
{
    extern __shared__ unsigned short smraw[];
    const uint32_t u0 = smem_u32(smraw);

    const int tid = threadIdx.x;
    const int lane = tid & 31;
    const int w = tid >> 5;
    const int wm = w >> 2;          // 0..1 -> 64 rows each
    const int wn = w & 3;           // 0..3 -> 32 cols each
    const int m0 = blockIdx.y * GBM;
    const int n0 = blockIdx.x * 128;
    const int bz = blockIdx.z;

    // per-lane ldmatrix row/col offsets
    const int aRow = wm * 64 + (lane & 7) + ((lane >> 3) & 1) * 8;  // + mi*16
    const int aCol = ((lane >> 4) & 1) * 8;                         // + kk
    const int bRow = wn * 32 + (lane & 7) + ((lane >> 4) & 1) * 8;  // + nio*16
    const int bCol = ((lane >> 3) & 1) * 8;                         // + kk

    const int ldr = tid >> 2;       // 0..63
    const int ldc = tid & 3;        // 0..3

    float c[4][4][4];
#pragma unroll
    for (int i = 0; i < 4; ++i)
#pragma unroll
        for (int j = 0; j < 4; ++j)
#pragma unroll
            for (int q = 0; q < 4; ++q) c[i][j][q] = 0.f;

    auto load_tile = [&](int kt, int s) {
        const int k0 = kt * GBK;
        int dlt = 0, i0 = k0;
        if (CONVB) { dlt = k0 / CINp; i0 = k0 - dlt * CINp; }
        const uint32_t sbase = u0 + (uint32_t)s * GSTAGE_B;
#pragma unroll
        for (int u = 0; u < 2; ++u) {
            const int r = ldr + u * 64;
            const uint32_t so = (uint32_t)((r * GLDS + ldc * 8) * 2);
            const size_t ga = (size_t)(m0 + r) * K + k0 + ldc * 8;
            cp16(sbase + so, Ahi + ga);
            cp16(sbase + GTILE * 2 + so, Alo + ga);
            size_t gb;
            if (CONVB) gb = (size_t)((size_t)bz * XTR + n0 + r + dlt) * CINp + i0 + ldc * 8;
            else       gb = (size_t)(n0 + r) * K + k0 + ldc * 8;
            cp16(sbase + 2 * GTILE * 2 + so, Bhi + gb);
            cp16(sbase + 3 * GTILE * 2 + so, Blo + gb);
        }
        asm volatile("cp.async.commit_group;" ::: "memory");
    };

    auto compute_tile = [&](int s) {
        const uint32_t uAh = u0 + (uint32_t)s * GSTAGE_B;
        const uint32_t uAl = uAh + GTILE * 2;
        const uint32_t uBh = uAl + GTILE * 2;
        const uint32_t uBl = uBh + GTILE * 2;
#pragma unroll
        for (int ks = 0; ks < 2; ++ks) {
            const int kk = ks * 16;
            uint32_t ah[4][4], al[4][4];
#pragma unroll
            for (int mi = 0; mi < 4; ++mi) {
                uint32_t off = (uint32_t)(((aRow + mi * 16) * GLDS + kk + aCol) * 2);
                LDSM_X4(ah[mi][0], ah[mi][1], ah[mi][2], ah[mi][3], uAh + off);
                LDSM_X4(al[mi][0], al[mi][1], al[mi][2], al[mi][3], uAl + off);
            }
            uint32_t bh[4][2], bl[4][2];
#pragma unroll
            for (int nio = 0; nio < 2; ++nio) {
                uint32_t off = (uint32_t)(((bRow + nio * 16) * GLDS + kk + bCol) * 2);
                uint32_t r0, r1, r2, r3;
                LDSM_X4(r0, r1, r2, r3, uBh + off);
                bh[nio * 2][0] = r0; bh[nio * 2][1] = r1;
                bh[nio * 2 + 1][0] = r2; bh[nio * 2 + 1][1] = r3;
                LDSM_X4(r0, r1, r2, r3, uBl + off);
                bl[nio * 2][0] = r0; bl[nio * 2][1] = r1;
                bl[nio * 2 + 1][0] = r2; bl[nio * 2 + 1][1] = r3;
            }
#pragma unroll
            for (int mi = 0; mi < 4; ++mi)
#pragma unroll
                for (int ni = 0; ni < 4; ++ni) {
                    mma16816(c[mi][ni], ah[mi][0], ah[mi][1], ah[mi][2], ah[mi][3],
                             bh[ni][0], bh[ni][1]);
                    mma16816(c[mi][ni], ah[mi][0], ah[mi][1], ah[mi][2], ah[mi][3],
                             bl[ni][0], bl[ni][1]);
                    mma16816(c[mi][ni], al[mi][0], al[mi][1], al[mi][2], al[mi][3],
                             bh[ni][0], bh[ni][1]);
                }
        }
    };

    const int nkt = K / GBK;
    load_tile(0, 0);
    for (int kt = 0; kt < nkt; ++kt) {
        if (kt + 1 < nkt) {
            load_tile(kt + 1, (kt + 1) & 1);
            asm volatile("cp.async.wait_group 1;" ::: "memory");
        } else {
            asm volatile("cp.async.wait_group 0;" ::: "memory");
        }
        __syncthreads();
        compute_tile(kt & 1);
        __syncthreads();
    }

    // ---------------- epilogue from fragments ----------------
#pragma unroll
    for (int mi = 0; mi < 4; ++mi) {
#pragma unroll
        for (int ni = 0; ni < 4; ++ni) {
            const int col = n0 + wn * 32 + ni * 8 + (lane & 3) * 2;
#pragma unroll
            for (int half = 0; half < 2; ++half) {
                const int row = m0 + wm * 64 + mi * 16 + (lane >> 2) + half * 8;
                const float v0r = c[mi][ni][half * 2];
                const float v1r = c[mi][ni][half * 2 + 1];
                if (EPI == 0) {
                    float2 v;
                    v.x = v0r + bias[col];
                    v.y = v1r + bias[col + 1];
                    *(float2*)(outf + (size_t)row * POSE + col) = v;
                } else if (EPI == 1) {
                    unsigned int lo;
                    unsigned int hi = split_pack(v0r + bias[col], v1r + bias[col + 1], &lo);
                    *(unsigned int*)(outhi + (size_t)row * POSE + col) = hi;
                    *(unsigned int*)(outlo + (size_t)row * POSE + col) = lo;
                } else {
                    const int och = row;
                    if (och < PRED) {
                        const float cb = bias[och];
                        const float sc = bng[och] * rsqrtf(bnv[och] + EPS);
                        const float mo = bnm[och], bo = bnb[och];
                        float v0 = (fmaxf(v0r + cb, 0.f) - mo) * sc + bo;
                        float v1 = (fmaxf(v1r + cb, 0.f) - mo) * sc + bo;
                        if (EPI == 3) {
                            float2 v; v.x = v0; v.y = v1;
                            *(float2*)(outf + (size_t)((size_t)bz * PRED + och) * POSE + col) = v;
                        } else {
                            size_t oi0 = (size_t)((size_t)bz * XTR + col + 1) * CIN2P + och;
                            size_t oi1 = (size_t)((size_t)bz * XTR + col + 2) * CIN2P + och;
                            split_bf16(v0, &outhi[oi0], &outlo[oi0]);
                            split_bf16(v1, &outhi[oi1], &outlo[oi1]);
                        }
                    }
                }
            }
        }
    }
}

// ---------------- conversion kernels ----------------
__global__ void cvt_flat(const float* __restrict__ s, unsigned short* __restrict__ hi,
                         unsigned short* __restrict__ lo, int n)
{
    for (int i = blockIdx.x * blockDim.x + threadIdx.x; i < n; i += gridDim.x * blockDim.x)
        split_bf16(s[i], &hi[i], &lo[i]);
}

__global__ void cvt_concat(const float* __restrict__ x, const float* __restrict__ p2,
                           unsigned short* __restrict__ hi, unsigned short* __restrict__ lo)
{
    int m = blockIdx.x;
    int b = m / FRAMES, f = m - b * FRAMES;
    const float* src = (f < PRIOR) ? x + ((size_t)b * PRIOR + f) * POSE
                                   : p2 + ((size_t)b * PRED + (f - PRIOR)) * POSE;
    size_t dst = (size_t)m * POSE;
    for (int ci = threadIdx.x; ci < POSE; ci += 256)
        split_bf16(src[ci], &hi[dst + ci], &lo[dst + ci]);
}

__global__ void cvt_convw(const float* __restrict__ wsrc, unsigned short* __restrict__ hi,
                          unsigned short* __restrict__ lo, int CIN, int CINp)
{
    int total = PRED * CIN * 3;
    int KC = 3 * CINp;
    for (int idx = blockIdx.x * blockDim.x + threadIdx.x; idx < total; idx += gridDim.x * blockDim.x) {
        int o = idx / (CIN * 3);
        int rem = idx - o * (CIN * 3);
        int i = rem / 3, d = rem - i * 3;
        size_t dst = (size_t)o * KC + (size_t)d * CINp + i;
        split_bf16(wsrc[idx], &hi[dst], &lo[dst]);
    }
}

__global__ void cvt_xT(const float* __restrict__ x, unsigned short* __restrict__ hi,
                       unsigned short* __restrict__ lo)
{
    __shared__ float t[64][65];
    int b = blockIdx.y, h0 = blockIdx.x * 64;
    for (int idx = threadIdx.x; idx < PRIOR * 64; idx += 256) {
        int i = idx >> 6, h = idx & 63;
        t[h][i] = x[((size_t)b * PRIOR + i) * POSE + h0 + h];
    }
    __syncthreads();
    for (int idx = threadIdx.x; idx < 64 * PRIOR; idx += 256) {
        int h = idx / PRIOR, i = idx - h * PRIOR;
        size_t dst = ((size_t)b * XTR + h0 + h + 1) * CIN1P + i;
        split_bf16(t[h][i], &hi[dst], &lo[dst]);
    }
}

// ---------------- FFMA NT GEMM (encoders); DUAL: W row n < Nsplit -> Wa else Wb --------
template <int BM, int BN, int BK, int TM, int TN, bool DUAL>
__global__ __launch_bounds__((BM / TM) * (BN / TN))
void sgemm_nt(const float* __restrict__ A, long lda,
              const float* __restrict__ W, const float* __restrict__ Wb,
              const float* __restrict__ bias, const float* __restrict__ biasb,
              int Nsplit,
              float* __restrict__ C, int ldc,
              int M, int N, int K)
{
    constexpr int THREADS = (BM / TM) * (BN / TN);
    constexpr int ASLOTS = BM * BK / THREADS;
    constexpr int BSLOTS = BN * BK / THREADS;
    __shared__ float As[BK][BM + 4];
    __shared__ float Bs[BK][BN + 4];
    const int tid = threadIdx.x;
    const int bm = blockIdx.y * BM;
    const int bn = blockIdx.x * BN;
    const int tx = tid % (BN / TN);
    const int ty = tid / (BN / TN);

    float acc[TM][TN];
#pragma unroll
    for (int i = 0; i < TM; ++i)
#pragma unroll
        for (int j = 0; j < TN; ++j) acc[i][j] = 0.f;

    for (int k0 = 0; k0 < K; k0 += BK) {
#pragma unroll
        for (int j = 0; j < ASLOTS; ++j) {
            int s = tid + j * THREADS;
            int kl = s % BK, ml = s / BK;
            int k = k0 + kl, m = bm + ml;
            As[kl][ml] = (k < K && m < M) ? A[(long)m * lda + k] : 0.f;
        }
#pragma unroll
        for (int j = 0; j < BSLOTS; ++j) {
            int s = tid + j * THREADS;
            int kl = s % BK, nl = s / BK;
            int k = k0 + kl, n = bn + nl;
            float v = 0.f;
            if (k < K && n < N) {
                const float* wr = (!DUAL || n < Nsplit) ? (W + (long)n * K)
                                                        : (Wb + (long)(n - Nsplit) * K);
                v = wr[k];
            }
            Bs[kl][nl] = v;
        }
        __syncthreads();
#pragma unroll
        for (int kk = 0; kk < BK; ++kk) {
            float a[TM], b[TN];
#pragma unroll
            for (int i = 0; i < TM; ++i) a[i] = As[kk][ty * TM + i];
#pragma unroll
            for (int j = 0; j < TN; ++j) b[j] = Bs[kk][tx * TN + j];
#pragma unroll
            for (int i = 0; i < TM; ++i)
#pragma unroll
                for (int j = 0; j < TN; ++j) acc[i][j] += a[i] * b[j];
        }
        __syncthreads();
    }
#pragma unroll
    for (int i = 0; i < TM; ++i) {
        int m = bm + ty * TM + i;
        if (m >= M) continue;
#pragma unroll
        for (int j = 0; j < TN; ++j) {
            int n = bn + tx * TN + j;
            if (n < N) {
                float bv = (!DUAL || n < Nsplit) ? bias[n] : biasb[n - Nsplit];
                C[(long)m * ldc + n] = acc[i][j] + bv;
            }
        }
    }
}

// ---------------- gate kernels ----------------
__global__ void sp_gate_kernel(const float* __restrict__ mem, float* __restrict__ p)
{
    int b = blockIdx.x;
    int tid = threadIdx.x;
    int w = tid >> 5, lane = tid & 31;
    __shared__ float sig_s[CHUNK];
    const float* pm = mem + (long)b * POSE;
    const float* pc = p + (long)b * PRED * POSE + (long)w * POSE;
    float s = 0.f;
    for (int d = lane; d < POSE; d += 32) s += pm[d] * pc[d];
#pragma unroll
    for (int o = 16; o; o >>= 1) s += __shfl_xor_sync(0xffffffffu, s, o);
    if (lane == 0) sig_s[w] = 1.f / (1.f + expf(-s));
    __syncthreads();
    float* pb = p + (long)b * PRED * POSE;
    for (int idx = tid; idx < CHUNK * POSE; idx += 320) {
        int cc = idx / POSE, d = idx - cc * POSE;
        float g = sig_s[cc];
        pb[idx] = g * pb[idx] + (1.f - g) * pm[d];
    }
}

__global__ void tm_t_kernel(const float* __restrict__ mem2, const float* __restrict__ penc,
                            float* __restrict__ t)
{
    int d = blockIdx.x;
    int tid = threadIdx.x;
    float acc[CHUNK];
#pragma unroll
    for (int cc = 0; cc < CHUNK; ++cc) acc[cc] = 0.f;
    for (int b = tid; b < BATCH; b += 64) {
        float m = mem2[(long)b * POSE + d];
        const float* pr = penc + (long)b * CHUNK;
#pragma unroll
        for (int cc = 0; cc < CHUNK; ++cc) acc[cc] += m * pr[cc];
    }
    __shared__ float red[64][CHUNK];
#pragma unroll
    for (int cc = 0; cc < CHUNK; ++cc) red[tid][cc] = acc[cc];
    __syncthreads();
    for (int off = 32; off >= 1; off >>= 1) {
        if (tid < off)
#pragma unroll
            for (int cc = 0; cc < CHUNK; ++cc) red[tid][cc] += red[tid + off][cc];
        __syncthreads();
    }
    if (tid == 0)
#pragma unroll
        for (int cc = 0; cc < CHUNK; ++cc) t[(long)d * CHUNK + cc] = red[0][cc];
}

__global__ void tm_apply_kernel(const float* __restrict__ mem2, const float* __restrict__ t,
                                float* __restrict__ p)
{
    int b = blockIdx.x;
    int tid = threadIdx.x;
    float acc[CHUNK];
#pragma unroll
    for (int cc = 0; cc < CHUNK; ++cc) acc[cc] = 0.f;
    const float* mb = mem2 + (long)b * POSE;
    for (int d = tid; d < POSE; d += 256) {
        float m = mb[d];
        const float* tr = t + (long)d * CHUNK;
#pragma unroll
        for (int cc = 0; cc < CHUNK; ++cc) acc[cc] += m * tr[cc];
    }
    __shared__ float red[256][CHUNK];
    __shared__ float soft[CHUNK];
#pragma unroll
    for (int cc = 0; cc < CHUNK; ++cc) red[tid][cc] = acc[cc];
    __syncthreads();
    for (int off = 128; off >= 1; off >>= 1) {
        if (tid < off)
#pragma unroll
            for (int cc = 0; cc < CHUNK; ++cc) red[tid][cc] += red[tid + off][cc];
        __syncthreads();
    }
    if (tid == 0) {
        float mx = red[0][0];
#pragma unroll
        for (int cc = 1; cc < CHUNK; ++cc) mx = fmaxf(mx, red[0][cc]);
        float sum = 0.f, e[CHUNK];
#pragma unroll
        for (int cc = 0; cc < CHUNK; ++cc) { e[cc] = expf(red[0][cc] - mx); sum += e[cc]; }
        float inv = 1.f / sum;
#pragma unroll
        for (int cc = 0; cc < CHUNK; ++cc) soft[cc] = e[cc] * inv;
    }
    __syncthreads();
    float* pb = p + (long)b * PRED * POSE;
    for (int idx = tid; idx < CHUNK * POSE; idx += 256) {
        int cc = idx / POSE;
        pb[idx] *= (1.f + soft[cc]);
    }
}

// ---------------- host launcher ----------------
extern "C" void kernel_launch(void* const* d_in, const int* in_sizes, int n_in,
                              void* d_out, int out_size)
{
    (void)in_sizes; (void)n_in; (void)out_size;
    const float* x       = (const float*)d_in[0];
    const float* conv1_w = (const float*)d_in[1];
    const float* conv1_b = (const float*)d_in[2];
    const float* bn1_g   = (const float*)d_in[3];
    const float* bn1_b   = (const float*)d_in[4];
    const float* bn1_m   = (const float*)d_in[5];
    const float* bn1_v   = (const float*)d_in[6];
    const float* conv2_w = (const float*)d_in[7];
    const float* conv2_b = (const float*)d_in[8];
    const float* bn2_g   = (const float*)d_in[9];
    const float* bn2_b   = (const float*)d_in[10];
    const float* bn2_m   = (const float*)d_in[11];
    const float* bn2_v   = (const float*)d_in[12];
    const float* sp_w1   = (const float*)d_in[13];
    const float* sp_b1   = (const float*)d_in[14];
    const float* sp_w2   = (const float*)d_in[15];
    const float* sp_b2   = (const float*)d_in[16];
    const float* tmc_w1  = (const float*)d_in[17];
    const float* tmc_b1  = (const float*)d_in[18];
    const float* tmc_w2  = (const float*)d_in[19];
    const float* tmc_b2  = (const float*)d_in[20];
    const float* tmm_w1  = (const float*)d_in[21];
    const float* tmm_b1  = (const float*)d_in[22];
    const float* tmm_w2  = (const float*)d_in[23];
    const float* tmm_b2  = (const float*)d_in[24];
    const float* post_w1 = (const float*)d_in[25];
    const float* post_b1 = (const float*)d_in[26];
    const float* post_w2 = (const float*)d_in[27];
    const float* post_b2 = (const float*)d_in[28];

    unsigned short *Ahi, *Alo, *Hhi, *Hlo, *W1hi, *W1lo, *W2hi, *W2lo;
    unsigned short *Xthi, *Xtlo, *P1hi, *P1lo, *Wc1hi, *Wc1lo, *Wc2hi, *Wc2lo;
    float *p2, *tmp, *mem, *mem2, *s1, *penc, *t;
    cudaGetSymbolAddress((void**)&Ahi, g_Ahi);   cudaGetSymbolAddress((void**)&Alo, g_Alo);
    cudaGetSymbolAddress((void**)&Hhi, g_Hhi);   cudaGetSymbolAddress((void**)&Hlo, g_Hlo);
    cudaGetSymbolAddress((void**)&W1hi, g_W1hi); cudaGetSymbolAddress((void**)&W1lo, g_W1lo);
    cudaGetSymbolAddress((void**)&W2hi, g_W2hi); cudaGetSymbolAddress((void**)&W2lo, g_W2lo);
    cudaGetSymbolAddress((void**)&Xthi, g_Xthi); cudaGetSymbolAddress((void**)&Xtlo, g_Xtlo);
    cudaGetSymbolAddress((void**)&P1hi, g_P1hi); cudaGetSymbolAddress((void**)&P1lo, g_P1lo);
    cudaGetSymbolAddress((void**)&Wc1hi, g_Wc1hi); cudaGetSymbolAddress((void**)&Wc1lo, g_Wc1lo);
    cudaGetSymbolAddress((void**)&Wc2hi, g_Wc2hi); cudaGetSymbolAddress((void**)&Wc2lo, g_Wc2lo);
    cudaGetSymbolAddress((void**)&p2, g_p2);
    cudaGetSymbolAddress((void**)&tmp, g_tmp);
    cudaGetSymbolAddress((void**)&mem, g_mem);
    cudaGetSymbolAddress((void**)&mem2, g_mem2);
    cudaGetSymbolAddress((void**)&s1, g_s1);
    cudaGetSymbolAddress((void**)&penc, g_penc);
    cudaGetSymbolAddress((void**)&t, g_t);

    cudaFuncSetAttribute(mma_gemm<0, false>, cudaFuncAttributeMaxDynamicSharedMemorySize, GSMEM_B);
    cudaFuncSetAttribute(mma_gemm<1, false>, cudaFuncAttributeMaxDynamicSharedMemorySize, GSMEM_B);
    cudaFuncSetAttribute(mma_gemm<2, true>,  cudaFuncAttributeMaxDynamicSharedMemorySize, GSMEM_B);
    cudaFuncSetAttribute(mma_gemm<3, true>,  cudaFuncAttributeMaxDynamicSharedMemorySize, GSMEM_B);

    // conversions
    cvt_flat<<<512, 256>>>(post_w1, W1hi, W1lo, POSE * POSE);
    cvt_flat<<<512, 256>>>(post_w2, W2hi, W2lo, POSE * POSE);
    cvt_convw<<<128, 256>>>(conv1_w, Wc1hi, Wc1lo, PRIOR, CIN1P);
    cvt_convw<<<256, 256>>>(conv2_w, Wc2hi, Wc2lo, PRED, CIN2P);
    cvt_xT<<<dim3(POSE / 64, BATCH), 256>>>(x, Xthi, Xtlo);

    // conv1: W[180(pad256),192] @ XT^T -> P1T bf16 hi/lo (relu+bn fused, transposed out)
    mma_gemm<2, true><<<dim3(POSE / 128, 2, BATCH), 256, GSMEM_B>>>(
        Wc1hi, Wc1lo, Xthi, Xtlo, KC1, CIN1P,
        conv1_b, bn1_g, bn1_b, bn1_m, bn1_v, nullptr, P1hi, P1lo);
    // conv2: W[180(pad256),576] @ P1T^T -> p2 fp32 (relu+bn fused)
    mma_gemm<3, true><<<dim3(POSE / 128, 2, BATCH), 256, GSMEM_B>>>(
        Wc2hi, Wc2lo, P1hi, P1lo, KC2, CIN2P,
        conv2_b, bn2_g, bn2_b, bn2_m, bn2_v, p2, nullptr, nullptr);

    // encoders (FFMA) + gates: sp & tmc layer-1 merged into one [256,1536,7680] launch
    const float* tail = x + (PRIOR - CHUNK) * POSE;
    sgemm_nt<32, 128, 16, 4, 8, true><<<dim3(1536 / 128, BATCH / 32), 128>>>(
        tail, (long)PRIOR * POSE, sp_w1, tmc_w1, sp_b1, tmc_b1, POSE,
        tmp, 2 * POSE, BATCH, 2 * POSE, CHUNK * POSE);
    sgemm_nt<32, 128, 16, 4, 8, false><<<dim3(POSE / 128, BATCH / 32), 128>>>(
        tmp, 2 * POSE, sp_w2, nullptr, sp_b2, nullptr, POSE,
        mem, POSE, BATCH, POSE, POSE);
    sgemm_nt<32, 128, 16, 4, 8, false><<<dim3(POSE / 128, BATCH / 32), 128>>>(
        tmp + POSE, 2 * POSE, tmc_w2, nullptr, tmc_b2, nullptr, POSE,
        mem2, POSE, BATCH, POSE, POSE);
    sp_gate_kernel<<<BATCH, CHUNK * 32>>>(mem, p2);
    sgemm_nt<32, 128, 16, 4, 8, false><<<dim3(1, BATCH / 32), 128>>>(
        p2, (long)PRED * POSE, tmm_w1, nullptr, tmm_b1, nullptr, CHUNK,
        s1, CHUNK, BATCH, CHUNK, CHUNK * POSE);
    sgemm_nt<32, 128, 16, 4, 8, false><<<dim3(1, BATCH / 32), 128>>>(
        s1, CHUNK, tmm_w2, nullptr, tmm_b2, nullptr, CHUNK,
        penc, CHUNK, BATCH, CHUNK, CHUNK);
    tm_t_kernel<<<POSE, 64>>>(mem2, penc, t);
    tm_apply_kernel<<<BATCH, 256>>>(mem2, t, p2);

    // post header on HMMA tensor path
    cvt_concat<<<MROWS, 256>>>(x, p2, Ahi, Alo);
    mma_gemm<1, false><<<dim3(POSE / 128, MROWS / 128), 256, GSMEM_B>>>(
        Ahi, Alo, W1hi, W1lo, POSE, 0,
        post_b1, nullptr, nullptr, nullptr, nullptr, nullptr, Hhi, Hlo);
    mma_gemm<0, false><<<dim3(POSE / 128, MROWS / 128), 256, GSMEM_B>>>(
        Hhi, Hlo, W2hi, W2lo, POSE, 0,
        post_b2, nullptr, nullptr, nullptr, nullptr, (float*)d_out, nullptr, nullptr);
}

// round 10
// speedup vs baseline: 3.1664x; 1.1876x over previous
#include <cuda_runtime.h>
#include <cuda_fp16.h>
#include <math.h>
#include <stdint.h>

#define BATCH  256
#define PRIOR  60
#define FRAMES 240
#define POSE   768
#define CHUNK  10
#define PRED   180
#define EPS    1e-5f
#define MROWS  (BATCH * FRAMES)
#define CIN1P  64
#define CIN2P  192
#define KC1    (3 * CIN1P)
#define KC2    (3 * CIN2P)
#define XTR    770

// ---------------- scratch (zero-initialized device globals; padding rows/channels are
// never written by any kernel, so they stay zero forever -> deterministic) -------------
__device__ unsigned short g_Ah[MROWS * POSE];                 // concat rows, fp16
__device__ unsigned short g_Hh[MROWS * POSE];                 // h1, fp16
__device__ unsigned short g_W1hi[POSE * POSE], g_W1lo[POSE * POSE];
__device__ unsigned short g_W2hi[POSE * POSE], g_W2lo[POSE * POSE];
__device__ unsigned short g_Xth[BATCH * XTR * CIN1P];         // xT padded, fp16
__device__ unsigned short g_P1h[BATCH * XTR * CIN2P];         // conv1 out (transposed), fp16
__device__ unsigned short g_Wc1hi[256 * KC1], g_Wc1lo[256 * KC1];
__device__ unsigned short g_Wc2hi[256 * KC2], g_Wc2lo[256 * KC2];
__device__ float g_p2[BATCH * PRED * POSE];
__device__ float g_tmp[BATCH * 2 * POSE];   // stacked sp|tmc layer-1 outputs, ld = 1536
__device__ float g_mem[BATCH * POSE];
__device__ float g_mem2[BATCH * POSE];
__device__ float g_s1[BATCH * CHUNK];
__device__ float g_penc[BATCH * CHUNK];
__device__ float g_t[POSE * CHUNK];

// ---------------- helpers ----------------
__device__ __forceinline__ uint32_t smem_u32(const void* p) {
    uint32_t a;
    asm("{ .reg .u64 t; cvta.to.shared.u64 t, %1; cvt.u32.u64 %0, t; }" : "=r"(a) : "l"(p));
    return a;
}
__device__ __forceinline__ void cp16(uint32_t dst, const void* src) {
    asm volatile("cp.async.cg.shared.global [%0], [%1], 16;" :: "r"(dst), "l"(src));
}

#define LDSM_X4(r0, r1, r2, r3, addr) \
    asm volatile("ldmatrix.sync.aligned.m8n8.x4.shared.b16 {%0, %1, %2, %3}, [%4];" \
        : "=r"(r0), "=r"(r1), "=r"(r2), "=r"(r3) : "r"(addr))

__device__ __forceinline__ void mma16816(float c[4], uint32_t a0, uint32_t a1, uint32_t a2, uint32_t a3,
                                         uint32_t b0, uint32_t b1) {
    asm volatile("mma.sync.aligned.m16n8k16.row.col.f32.f16.f16.f32 "
                 "{%0, %1, %2, %3}, {%4, %5, %6, %7}, {%8, %9}, {%0, %1, %2, %3};"
                 : "+f"(c[0]), "+f"(c[1]), "+f"(c[2]), "+f"(c[3])
                 : "r"(a0), "r"(a1), "r"(a2), "r"(a3), "r"(b0), "r"(b1));
}

__device__ __forceinline__ unsigned short f2h(float v) {
    __half h = __float2half_rn(v);
    return *(unsigned short*)&h;
}
__device__ __forceinline__ void split_fp16(float v, unsigned short* hp, unsigned short* lp) {
    __half h = __float2half_rn(v);
    __half l = __float2half_rn(v - __half2float(h));
    *hp = *(unsigned short*)&h;
    *lp = *(unsigned short*)&l;
}

// ---------------- HMMA fp16 2-pass NT GEMM (cp.async double-buffered) ------------------
// C[128x128 tile] = A[128,K] @ B[128rows,K]^T
// CONVB=true : A = conv weights SPLIT hi/lo, B = activations single fp16 (shifted loader)
//              passes: Ah*B + Al*B
// CONVB=false: A = activations single fp16, B = weights SPLIT hi/lo
//              passes: A*Bh + A*Bl
// EPI 0: +bias(n) -> fp32 outf (ld POSE)
// EPI 1: +bias(n) -> fp16 outh (ld POSE)
// EPI 2: +convbias(m), relu, BN(m) -> transposed fp16 P1T[bz][h+1][och] (ld CIN2P)
// EPI 3: +convbias(m), relu, BN(m) -> fp32 channel-major p2[bz][och][h]
#define GBM 128
#define GBK 32
#define GLDS (GBK + 8)
#define GTILE (GBM * GLDS)                  // shorts per operand tile (5120)
#define GSTAGE_B (3 * GTILE * 2)            // bytes per stage (30720)
#define GSMEM_B (2 * GSTAGE_B)              // 61440

template <int EPI, bool CONVB>
__global__ __launch_bounds__(256)
void mma_gemm(const unsigned short* __restrict__ A0, const unsigned short* __restrict__ A1,
              const unsigned short* __restrict__ B0, const unsigned short* __restrict__ B1,
              int K, int CINp,
              const float* __restrict__ bias,
              const float* __restrict__ bng, const float* __restrict__ bnb,
              const float* __restrict__ bnm, const float* __restrict__ bnv,
              float* __restrict__ outf, unsigned short* __restrict__ outh)
{
    extern __shared__ unsigned short smraw[];
    const uint32_t u0 = smem_u32(smraw);

    const int tid = threadIdx.x;
    const int lane = tid & 31;
    const int w = tid >> 5;
    const int wm = w >> 2;          // 0..1 -> 64 rows each
    const int wn = w & 3;           // 0..3 -> 32 cols each
    const int m0 = blockIdx.y * GBM;
    const int n0 = blockIdx.x * 128;
    const int bz = blockIdx.z;

    const int aRow = wm * 64 + (lane & 7) + ((lane >> 3) & 1) * 8;  // + mi*16
    const int aCol = ((lane >> 4) & 1) * 8;
    const int bRow = wn * 32 + (lane & 7) + ((lane >> 4) & 1) * 8;  // + nio*16
    const int bCol = ((lane >> 3) & 1) * 8;

    const int ldr = tid >> 2;       // 0..63
    const int ldc = tid & 3;        // 0..3

    float c[4][4][4];
#pragma unroll
    for (int i = 0; i < 4; ++i)
#pragma unroll
        for (int j = 0; j < 4; ++j)
#pragma unroll
            for (int q = 0; q < 4; ++q) c[i][j][q] = 0.f;

    auto load_tile = [&](int kt, int s) {
        const int k0 = kt * GBK;
        int dlt = 0, i0 = k0;
        if (CONVB) { dlt = k0 / CINp; i0 = k0 - dlt * CINp; }
        const uint32_t sbase = u0 + (uint32_t)s * GSTAGE_B;
#pragma unroll
        for (int u = 0; u < 2; ++u) {
            const int r = ldr + u * 64;
            const uint32_t so = (uint32_t)((r * GLDS + ldc * 8) * 2);
            const size_t ga = (size_t)(m0 + r) * K + k0 + ldc * 8;
            size_t gb;
            if (CONVB) gb = (size_t)((size_t)bz * XTR + n0 + r + dlt) * CINp + i0 + ldc * 8;
            else       gb = (size_t)(n0 + r) * K + k0 + ldc * 8;
            if (CONVB) {
                cp16(sbase + so, A0 + ga);                 // weight hi
                cp16(sbase + GTILE * 2 + so, A1 + ga);     // weight lo
                cp16(sbase + 2 * GTILE * 2 + so, B0 + gb); // activation single
            } else {
                cp16(sbase + so, A0 + ga);                 // activation single
                cp16(sbase + GTILE * 2 + so, B0 + gb);     // weight hi
                cp16(sbase + 2 * GTILE * 2 + so, B1 + gb); // weight lo
            }
        }
        asm volatile("cp.async.commit_group;" ::: "memory");
    };

    auto compute_tile = [&](int s) {
        const uint32_t t0 = u0 + (uint32_t)s * GSTAGE_B;
        const uint32_t t1 = t0 + GTILE * 2;
        const uint32_t t2 = t1 + GTILE * 2;
#pragma unroll
        for (int ks = 0; ks < 2; ++ks) {
            const int kk = ks * 16;
            if (CONVB) {
                uint32_t ah[4][4], al[4][4];
#pragma unroll
                for (int mi = 0; mi < 4; ++mi) {
                    uint32_t off = (uint32_t)(((aRow + mi * 16) * GLDS + kk + aCol) * 2);
                    LDSM_X4(ah[mi][0], ah[mi][1], ah[mi][2], ah[mi][3], t0 + off);
                    LDSM_X4(al[mi][0], al[mi][1], al[mi][2], al[mi][3], t1 + off);
                }
                uint32_t b[4][2];
#pragma unroll
                for (int nio = 0; nio < 2; ++nio) {
                    uint32_t off = (uint32_t)(((bRow + nio * 16) * GLDS + kk + bCol) * 2);
                    uint32_t r0, r1, r2, r3;
                    LDSM_X4(r0, r1, r2, r3, t2 + off);
                    b[nio * 2][0] = r0; b[nio * 2][1] = r1;
                    b[nio * 2 + 1][0] = r2; b[nio * 2 + 1][1] = r3;
                }
#pragma unroll
                for (int mi = 0; mi < 4; ++mi)
#pragma unroll
                    for (int ni = 0; ni < 4; ++ni) {
                        mma16816(c[mi][ni], ah[mi][0], ah[mi][1], ah[mi][2], ah[mi][3],
                                 b[ni][0], b[ni][1]);
                        mma16816(c[mi][ni], al[mi][0], al[mi][1], al[mi][2], al[mi][3],
                                 b[ni][0], b[ni][1]);
                    }
            } else {
                uint32_t a[4][4];
#pragma unroll
                for (int mi = 0; mi < 4; ++mi) {
                    uint32_t off = (uint32_t)(((aRow + mi * 16) * GLDS + kk + aCol) * 2);
                    LDSM_X4(a[mi][0], a[mi][1], a[mi][2], a[mi][3], t0 + off);
                }
                uint32_t bh[4][2], bl[4][2];
#pragma unroll
                for (int nio = 0; nio < 2; ++nio) {
                    uint32_t off = (uint32_t)(((bRow + nio * 16) * GLDS + kk + bCol) * 2);
                    uint32_t r0, r1, r2, r3;
                    LDSM_X4(r0, r1, r2, r3, t1 + off);
                    bh[nio * 2][0] = r0; bh[nio * 2][1] = r1;
                    bh[nio * 2 + 1][0] = r2; bh[nio * 2 + 1][1] = r3;
                    LDSM_X4(r0, r1, r2, r3, t2 + off);
                    bl[nio * 2][0] = r0; bl[nio * 2][1] = r1;
                    bl[nio * 2 + 1][0] = r2; bl[nio * 2 + 1][1] = r3;
                }
#pragma unroll
                for (int mi = 0; mi < 4; ++mi)
#pragma unroll
                    for (int ni = 0; ni < 4; ++ni) {
                        mma16816(c[mi][ni], a[mi][0], a[mi][1], a[mi][2], a[mi][3],
                                 bh[ni][0], bh[ni][1]);
                        mma16816(c[mi][ni], a[mi][0], a[mi][1], a[mi][2], a[mi][3],
                                 bl[ni][0], bl[ni][1]);
                    }
            }
        }
    };

    const int nkt = K / GBK;
    load_tile(0, 0);
    for (int kt = 0; kt < nkt; ++kt) {
        if (kt + 1 < nkt) {
            load_tile(kt + 1, (kt + 1) & 1);
            asm volatile("cp.async.wait_group 1;" ::: "memory");
        } else {
            asm volatile("cp.async.wait_group 0;" ::: "memory");
        }
        __syncthreads();
        compute_tile(kt & 1);
        __syncthreads();
    }

    // ---------------- epilogue from fragments ----------------
#pragma unroll
    for (int mi = 0; mi < 4; ++mi) {
#pragma unroll
        for (int ni = 0; ni < 4; ++ni) {
            const int col = n0 + wn * 32 + ni * 8 + (lane & 3) * 2;
#pragma unroll
            for (int half = 0; half < 2; ++half) {
                const int row = m0 + wm * 64 + mi * 16 + (lane >> 2) + half * 8;
                const float v0r = c[mi][ni][half * 2];
                const float v1r = c[mi][ni][half * 2 + 1];
                if (EPI == 0) {
                    float2 v;
                    v.x = v0r + bias[col];
                    v.y = v1r + bias[col + 1];
                    *(float2*)(outf + (size_t)row * POSE + col) = v;
                } else if (EPI == 1) {
                    unsigned int hv = (unsigned int)f2h(v0r + bias[col])
                                    | ((unsigned int)f2h(v1r + bias[col + 1]) << 16);
                    *(unsigned int*)(outh + (size_t)row * POSE + col) = hv;
                } else {
                    const int och = row;
                    if (och < PRED) {
                        const float cb = bias[och];
                        const float sc = bng[och] * rsqrtf(bnv[och] + EPS);
                        const float mo = bnm[och], bo = bnb[och];
                        float v0 = (fmaxf(v0r + cb, 0.f) - mo) * sc + bo;
                        float v1 = (fmaxf(v1r + cb, 0.f) - mo) * sc + bo;
                        if (EPI == 3) {
                            float2 v; v.x = v0; v.y = v1;
                            *(float2*)(outf + (size_t)((size_t)bz * PRED + och) * POSE + col) = v;
                        } else {
                            size_t oi0 = (size_t)((size_t)bz * XTR + col + 1) * CIN2P + och;
                            size_t oi1 = (size_t)((size_t)bz * XTR + col + 2) * CIN2P + och;
                            outh[oi0] = f2h(v0);
                            outh[oi1] = f2h(v1);
                        }
                    }
                }
            }
        }
    }
}

// ---------------- conversion kernels ----------------
__global__ void cvt_flat(const float* __restrict__ s, unsigned short* __restrict__ hi,
                         unsigned short* __restrict__ lo, int n)
{
    for (int i = blockIdx.x * blockDim.x + threadIdx.x; i < n; i += gridDim.x * blockDim.x)
        split_fp16(s[i], &hi[i], &lo[i]);
}

__global__ void cvt_concat(const float* __restrict__ x, const float* __restrict__ p2,
                           unsigned short* __restrict__ h)
{
    int m = blockIdx.x;
    int b = m / FRAMES, f = m - b * FRAMES;
    const float* src = (f < PRIOR) ? x + ((size_t)b * PRIOR + f) * POSE
                                   : p2 + ((size_t)b * PRED + (f - PRIOR)) * POSE;
    size_t dst = (size_t)m * POSE;
    for (int ci = threadIdx.x; ci < POSE; ci += 256)
        h[dst + ci] = f2h(src[ci]);
}

__global__ void cvt_convw(const float* __restrict__ wsrc, unsigned short* __restrict__ hi,
                          unsigned short* __restrict__ lo, int CIN, int CINp)
{
    int total = PRED * CIN * 3;
    int KC = 3 * CINp;
    for (int idx = blockIdx.x * blockDim.x + threadIdx.x; idx < total; idx += gridDim.x * blockDim.x) {
        int o = idx / (CIN * 3);
        int rem = idx - o * (CIN * 3);
        int i = rem / 3, d = rem - i * 3;
        size_t dst = (size_t)o * KC + (size_t)d * CINp + i;
        split_fp16(wsrc[idx], &hi[dst], &lo[dst]);
    }
}

__global__ void cvt_xT(const float* __restrict__ x, unsigned short* __restrict__ h)
{
    __shared__ float t[64][65];
    int b = blockIdx.y, h0 = blockIdx.x * 64;
    for (int idx = threadIdx.x; idx < PRIOR * 64; idx += 256) {
        int i = idx >> 6, hh = idx & 63;
        t[hh][i] = x[((size_t)b * PRIOR + i) * POSE + h0 + hh];
    }
    __syncthreads();
    for (int idx = threadIdx.x; idx < 64 * PRIOR; idx += 256) {
        int hh = idx / PRIOR, i = idx - hh * PRIOR;
        size_t dst = ((size_t)b * XTR + h0 + hh + 1) * CIN1P + i;
        h[dst] = f2h(t[hh][i]);
    }
}

// ---------------- FFMA NT GEMM (encoders); DUAL: W row n < Nsplit -> Wa else Wb --------
template <int BM, int BN, int BK, int TM, int TN, bool DUAL>
__global__ __launch_bounds__((BM / TM) * (BN / TN))
void sgemm_nt(const float* __restrict__ A, long lda,
              const float* __restrict__ W, const float* __restrict__ Wb,
              const float* __restrict__ bias, const float* __restrict__ biasb,
              int Nsplit,
              float* __restrict__ C, int ldc,
              int M, int N, int K)
{
    constexpr int THREADS = (BM / TM) * (BN / TN);
    constexpr int ASLOTS = BM * BK / THREADS;
    constexpr int BSLOTS = BN * BK / THREADS;
    __shared__ float As[BK][BM + 4];
    __shared__ float Bs[BK][BN + 4];
    const int tid = threadIdx.x;
    const int bm = blockIdx.y * BM;
    const int bn = blockIdx.x * BN;
    const int tx = tid % (BN / TN);
    const int ty = tid / (BN / TN);

    float acc[TM][TN];
#pragma unroll
    for (int i = 0; i < TM; ++i)
#pragma unroll
        for (int j = 0; j < TN; ++j) acc[i][j] = 0.f;

    for (int k0 = 0; k0 < K; k0 += BK) {
#pragma unroll
        for (int j = 0; j < ASLOTS; ++j) {
            int s = tid + j * THREADS;
            int kl = s % BK, ml = s / BK;
            int k = k0 + kl, m = bm + ml;
            As[kl][ml] = (k < K && m < M) ? A[(long)m * lda + k] : 0.f;
        }
#pragma unroll
        for (int j = 0; j < BSLOTS; ++j) {
            int s = tid + j * THREADS;
            int kl = s % BK, nl = s / BK;
            int k = k0 + kl, n = bn + nl;
            float v = 0.f;
            if (k < K && n < N) {
                const float* wr = (!DUAL || n < Nsplit) ? (W + (long)n * K)
                                                        : (Wb + (long)(n - Nsplit) * K);
                v = wr[k];
            }
            Bs[kl][nl] = v;
        }
        __syncthreads();
#pragma unroll
        for (int kk = 0; kk < BK; ++kk) {
            float a[TM], b[TN];
#pragma unroll
            for (int i = 0; i < TM; ++i) a[i] = As[kk][ty * TM + i];
#pragma unroll
            for (int j = 0; j < TN; ++j) b[j] = Bs[kk][tx * TN + j];
#pragma unroll
            for (int i = 0; i < TM; ++i)
#pragma unroll
                for (int j = 0; j < TN; ++j) acc[i][j] += a[i] * b[j];
        }
        __syncthreads();
    }
#pragma unroll
    for (int i = 0; i < TM; ++i) {
        int m = bm + ty * TM + i;
        if (m >= M) continue;
#pragma unroll
        for (int j = 0; j < TN; ++j) {
            int n = bn + tx * TN + j;
            if (n < N) {
                float bv = (!DUAL || n < Nsplit) ? bias[n] : biasb[n - Nsplit];
                C[(long)m * ldc + n] = acc[i][j] + bv;
            }
        }
    }
}

// ---------------- gate kernels ----------------
__global__ void sp_gate_kernel(const float* __restrict__ mem, float* __restrict__ p)
{
    int b = blockIdx.x;
    int tid = threadIdx.x;
    int w = tid >> 5, lane = tid & 31;
    __shared__ float sig_s[CHUNK];
    const float* pm = mem + (long)b * POSE;
    const float* pc = p + (long)b * PRED * POSE + (long)w * POSE;
    float s = 0.f;
    for (int d = lane; d < POSE; d += 32) s += pm[d] * pc[d];
#pragma unroll
    for (int o = 16; o; o >>= 1) s += __shfl_xor_sync(0xffffffffu, s, o);
    if (lane == 0) sig_s[w] = 1.f / (1.f + expf(-s));
    __syncthreads();
    float* pb = p + (long)b * PRED * POSE;
    for (int idx = tid; idx < CHUNK * POSE; idx += 320) {
        int cc = idx / POSE, d = idx - cc * POSE;
        float g = sig_s[cc];
        pb[idx] = g * pb[idx] + (1.f - g) * pm[d];
    }
}

__global__ void tm_t_kernel(const float* __restrict__ mem2, const float* __restrict__ penc,
                            float* __restrict__ t)
{
    int d = blockIdx.x;
    int tid = threadIdx.x;
    float acc[CHUNK];
#pragma unroll
    for (int cc = 0; cc < CHUNK; ++cc) acc[cc] = 0.f;
    for (int b = tid; b < BATCH; b += 64) {
        float m = mem2[(long)b * POSE + d];
        const float* pr = penc + (long)b * CHUNK;
#pragma unroll
        for (int cc = 0; cc < CHUNK; ++cc) acc[cc] += m * pr[cc];
    }
    __shared__ float red[64][CHUNK];
#pragma unroll
    for (int cc = 0; cc < CHUNK; ++cc) red[tid][cc] = acc[cc];
    __syncthreads();
    for (int off = 32; off >= 1; off >>= 1) {
        if (tid < off)
#pragma unroll
            for (int cc = 0; cc < CHUNK; ++cc) red[tid][cc] += red[tid + off][cc];
        __syncthreads();
    }
    if (tid == 0)
#pragma unroll
        for (int cc = 0; cc < CHUNK; ++cc) t[(long)d * CHUNK + cc] = red[0][cc];
}

__global__ void tm_apply_kernel(const float* __restrict__ mem2, const float* __restrict__ t,
                                float* __restrict__ p)
{
    int b = blockIdx.x;
    int tid = threadIdx.x;
    float acc[CHUNK];
#pragma unroll
    for (int cc = 0; cc < CHUNK; ++cc) acc[cc] = 0.f;
    const float* mb = mem2 + (long)b * POSE;
    for (int d = tid; d < POSE; d += 256) {
        float m = mb[d];
        const float* tr = t + (long)d * CHUNK;
#pragma unroll
        for (int cc = 0; cc < CHUNK; ++cc) acc[cc] += m * tr[cc];
    }
    __shared__ float red[256][CHUNK];
    __shared__ float soft[CHUNK];
#pragma unroll
    for (int cc = 0; cc < CHUNK; ++cc) red[tid][cc] = acc[cc];
    __syncthreads();
    for (int off = 128; off >= 1; off >>= 1) {
        if (tid < off)
#pragma unroll
            for (int cc = 0; cc < CHUNK; ++cc) red[tid][cc] += red[tid + off][cc];
        __syncthreads();
    }
    if (tid == 0) {
        float mx = red[0][0];
#pragma unroll
        for (int cc = 1; cc < CHUNK; ++cc) mx = fmaxf(mx, red[0][cc]);
        float sum = 0.f, e[CHUNK];
#pragma unroll
        for (int cc = 0; cc < CHUNK; ++cc) { e[cc] = expf(red[0][cc] - mx); sum += e[cc]; }
        float inv = 1.f / sum;
#pragma unroll
        for (int cc = 0; cc < CHUNK; ++cc) soft[cc] = e[cc] * inv;
    }
    __syncthreads();
    float* pb = p + (long)b * PRED * POSE;
    for (int idx = tid; idx < CHUNK * POSE; idx += 256) {
        int cc = idx / POSE;
        pb[idx] *= (1.f + soft[cc]);
    }
}

// ---------------- host launcher ----------------
extern "C" void kernel_launch(void* const* d_in, const int* in_sizes, int n_in,
                              void* d_out, int out_size)
{
    (void)in_sizes; (void)n_in; (void)out_size;
    const float* x       = (const float*)d_in[0];
    const float* conv1_w = (const float*)d_in[1];
    const float* conv1_b = (const float*)d_in[2];
    const float* bn1_g   = (const float*)d_in[3];
    const float* bn1_b   = (const float*)d_in[4];
    const float* bn1_m   = (const float*)d_in[5];
    const float* bn1_v   = (const float*)d_in[6];
    const float* conv2_w = (const float*)d_in[7];
    const float* conv2_b = (const float*)d_in[8];
    const float* bn2_g   = (const float*)d_in[9];
    const float* bn2_b   = (const float*)d_in[10];
    const float* bn2_m   = (const float*)d_in[11];
    const float* bn2_v   = (const float*)d_in[12];
    const float* sp_w1   = (const float*)d_in[13];
    const float* sp_b1   = (const float*)d_in[14];
    const float* sp_w2   = (const float*)d_in[15];
    const float* sp_b2   = (const float*)d_in[16];
    const float* tmc_w1  = (const float*)d_in[17];
    const float* tmc_b1  = (const float*)d_in[18];
    const float* tmc_w2  = (const float*)d_in[19];
    const float* tmc_b2  = (const float*)d_in[20];
    const float* tmm_w1  = (const float*)d_in[21];
    const float* tmm_b1  = (const float*)d_in[22];
    const float* tmm_w2  = (const float*)d_in[23];
    const float* tmm_b2  = (const float*)d_in[24];
    const float* post_w1 = (const float*)d_in[25];
    const float* post_b1 = (const float*)d_in[26];
    const float* post_w2 = (const float*)d_in[27];
    const float* post_b2 = (const float*)d_in[28];

    unsigned short *Ah, *Hh, *W1hi, *W1lo, *W2hi, *W2lo;
    unsigned short *Xth, *P1h, *Wc1hi, *Wc1lo, *Wc2hi, *Wc2lo;
    float *p2, *tmp, *mem, *mem2, *s1, *penc, *t;
    cudaGetSymbolAddress((void**)&Ah, g_Ah);
    cudaGetSymbolAddress((void**)&Hh, g_Hh);
    cudaGetSymbolAddress((void**)&W1hi, g_W1hi); cudaGetSymbolAddress((void**)&W1lo, g_W1lo);
    cudaGetSymbolAddress((void**)&W2hi, g_W2hi); cudaGetSymbolAddress((void**)&W2lo, g_W2lo);
    cudaGetSymbolAddress((void**)&Xth, g_Xth);
    cudaGetSymbolAddress((void**)&P1h, g_P1h);
    cudaGetSymbolAddress((void**)&Wc1hi, g_Wc1hi); cudaGetSymbolAddress((void**)&Wc1lo, g_Wc1lo);
    cudaGetSymbolAddress((void**)&Wc2hi, g_Wc2hi); cudaGetSymbolAddress((void**)&Wc2lo, g_Wc2lo);
    cudaGetSymbolAddress((void**)&p2, g_p2);
    cudaGetSymbolAddress((void**)&tmp, g_tmp);
    cudaGetSymbolAddress((void**)&mem, g_mem);
    cudaGetSymbolAddress((void**)&mem2, g_mem2);
    cudaGetSymbolAddress((void**)&s1, g_s1);
    cudaGetSymbolAddress((void**)&penc, g_penc);
    cudaGetSymbolAddress((void**)&t, g_t);

    cudaFuncSetAttribute(mma_gemm<0, false>, cudaFuncAttributeMaxDynamicSharedMemorySize, GSMEM_B);
    cudaFuncSetAttribute(mma_gemm<1, false>, cudaFuncAttributeMaxDynamicSharedMemorySize, GSMEM_B);
    cudaFuncSetAttribute(mma_gemm<2, true>,  cudaFuncAttributeMaxDynamicSharedMemorySize, GSMEM_B);
    cudaFuncSetAttribute(mma_gemm<3, true>,  cudaFuncAttributeMaxDynamicSharedMemorySize, GSMEM_B);

    // conversions
    cvt_flat<<<512, 256>>>(post_w1, W1hi, W1lo, POSE * POSE);
    cvt_flat<<<512, 256>>>(post_w2, W2hi, W2lo, POSE * POSE);
    cvt_convw<<<128, 256>>>(conv1_w, Wc1hi, Wc1lo, PRIOR, CIN1P);
    cvt_convw<<<256, 256>>>(conv2_w, Wc2hi, Wc2lo, PRED, CIN2P);
    cvt_xT<<<dim3(POSE / 64, BATCH), 256>>>(x, Xth);

    // conv1: W[180(pad256),192] @ XT^T -> P1T fp16 (relu+bn fused, transposed out)
    mma_gemm<2, true><<<dim3(POSE / 128, 2, BATCH), 256, GSMEM_B>>>(
        Wc1hi, Wc1lo, Xth, nullptr, KC1, CIN1P,
        conv1_b, bn1_g, bn1_b, bn1_m, bn1_v, nullptr, P1h);
    // conv2: W[180(pad256),576] @ P1T^T -> p2 fp32 (relu+bn fused)
    mma_gemm<3, true><<<dim3(POSE / 128, 2, BATCH), 256, GSMEM_B>>>(
        Wc2hi, Wc2lo, P1h, nullptr, KC2, CIN2P,
        conv2_b, bn2_g, bn2_b, bn2_m, bn2_v, p2, nullptr);

    // encoders (FFMA) + gates: sp & tmc layer-1 merged into one [256,1536,7680] launch
    const float* tail = x + (PRIOR - CHUNK) * POSE;
    sgemm_nt<32, 128, 16, 4, 8, true><<<dim3(1536 / 128, BATCH / 32), 128>>>(
        tail, (long)PRIOR * POSE, sp_w1, tmc_w1, sp_b1, tmc_b1, POSE,
        tmp, 2 * POSE, BATCH, 2 * POSE, CHUNK * POSE);
    sgemm_nt<32, 128, 16, 4, 8, false><<<dim3(POSE / 128, BATCH / 32), 128>>>(
        tmp, 2 * POSE, sp_w2, nullptr, sp_b2, nullptr, POSE,
        mem, POSE, BATCH, POSE, POSE);
    sgemm_nt<32, 128, 16, 4, 8, false><<<dim3(POSE / 128, BATCH / 32), 128>>>(
        tmp + POSE, 2 * POSE, tmc_w2, nullptr, tmc_b2, nullptr, POSE,
        mem2, POSE, BATCH, POSE, POSE);
    sp_gate_kernel<<<BATCH, CHUNK * 32>>>(mem, p2);
    sgemm_nt<32, 128, 16, 4, 8, false><<<dim3(1, BATCH / 32), 128>>>(
        p2, (long)PRED * POSE, tmm_w1, nullptr, tmm_b1, nullptr, CHUNK,
        s1, CHUNK, BATCH, CHUNK, CHUNK * POSE);
    sgemm_nt<32, 128, 16, 4, 8, false><<<dim3(1, BATCH / 32), 128>>>(
        s1, CHUNK, tmm_w2, nullptr, tmm_b2, nullptr, CHUNK,
        penc, CHUNK, BATCH, CHUNK, CHUNK);
    tm_t_kernel<<<POSE, 64>>>(mem2, penc, t);
    tm_apply_kernel<<<BATCH, 256>>>(mem2, t, p2);

    // post header on HMMA tensor path (fp16 2-pass, weights split)
    cvt_concat<<<MROWS, 256>>>(x, p2, Ah);
    mma_gemm<1, false><<<dim3(POSE / 128, MROWS / 128), 256, GSMEM_B>>>(
        Ah, nullptr, W1hi, W1lo, POSE, 0,
        post_b1, nullptr, nullptr, nullptr, nullptr, nullptr, Hh);
    mma_gemm<0, false><<<dim3(POSE / 128, MROWS / 128), 256, GSMEM_B>>>(
        Hh, nullptr, W2hi, W2lo, POSE, 0,
        post_b2, nullptr, nullptr, nullptr, nullptr, (float*)d_out, nullptr);
}